// round 9
// baseline (speedup 1.0000x reference)
#include <cuda_runtime.h>
#include <cuda_fp16.h>
#include <math.h>

#define NU 60001
#define NI 40001
#define NN 100002
#define DD 64
#define EE 600000
#define E2 (2*EE)
#define E2G (3*E2)
#define NB 2048
#define NCH 98   // ceil(NN/1024)

// ---- static device scratch ----
__device__ __align__(128) __half d_Z0 [NN * DD];      // rnG-scaled x0
__device__ __align__(128) __half d_Z1 [NN * DD];      // rnG^2 * s1
__device__ __align__(128) __half d_ALLh[NN * DD];     // plain ALL (shared hot gather src)
__device__ __align__(128) __half d_ZB [3 * NN * DD];  // rnB_g * s1_g (pre-scaled)
__device__ __align__(128) float  d_AU [NU * 3 * DD];  // all_user [u][3][64]
__device__ __align__(128) float  d_IF [NI * DD];      // item_final [i][64]
__device__ __align__(128) int    d_adj [3 * E2];      // branch adjacency
__device__ __align__(128) int    d_adjG[E2G];         // merged global adjacency
__device__ __align__(128) int    d_deg [3 * NN];
__device__ __align__(128) int    d_off [4 * (NN + 1)];  // 3 branches + global
__device__ __align__(128) int    d_cur [4 * NN];
__device__ __align__(128) int    d_sums[4 * NCH];
__device__ __align__(128) float  d_rnG [NN];
__device__ __align__(128) float  d_rnB [3 * NN];
__device__ float d_ACC[4];

// ---- convert inputs to fp16, pre-scaled by rnG ----
__global__ void k_conv(const float* __restrict__ ue, const float* __restrict__ ie,
                       const float* __restrict__ rnG, __half* __restrict__ z0) {
    int i = blockIdx.x * blockDim.x + threadIdx.x;       // half2 index
    if (i >= NN * DD / 2) return;
    int elem = i * 2;
    int n = i >> 5;
    const int UB = NU * DD;
    float2 v = (elem < UB) ? __ldg((const float2*)(ue + elem))
                           : __ldg((const float2*)(ie + (elem - UB)));
    float r = __ldg(rnG + n);
    ((__half2*)z0)[i] = __float22half2_rn(make_float2(v.x * r, v.y * r));
}

// ---- degree count ----
__global__ void k_degcnt(const int* __restrict__ eu, const int* __restrict__ ei,
                         int* __restrict__ deg) {
    int t = blockIdx.x * blockDim.x + threadIdx.x;
    if (t >= 3 * EE) return;
    int b = t / EE;
    atomicAdd(&deg[b * NN + eu[t]], 1);
    atomicAdd(&deg[b * NN + NU + ei[t]], 1);
}

// ---- 3-pass exclusive scan over 4 graphs (3 branch + merged global) ----
__global__ void k_scanA(const int* __restrict__ deg, int* __restrict__ off,
                        int* __restrict__ sums) {
    int g = blockIdx.x / NCH, c = blockIdx.x % NCH;
    int i = c * 1024 + threadIdx.x;
    int v = 0;
    if (i < NN)
        v = (g < 3) ? deg[g * NN + i]
                    : deg[i] + deg[NN + i] + deg[2 * NN + i];
    __shared__ int sd[1024];
    sd[threadIdx.x] = v;
    __syncthreads();
    for (int o = 1; o < 1024; o <<= 1) {
        int a = (threadIdx.x >= o) ? sd[threadIdx.x - o] : 0;
        __syncthreads();
        sd[threadIdx.x] += a;
        __syncthreads();
    }
    int inc = sd[threadIdx.x];
    if (i < NN) off[g * (NN + 1) + i] = inc - v;
    if (threadIdx.x == 1023) sums[g * NCH + c] = inc;
}

__global__ void k_scanB(int* __restrict__ sums) {
    int g = blockIdx.x, t = threadIdx.x;
    __shared__ int sd[128];
    int v = (t < NCH) ? sums[g * NCH + t] : 0;
    sd[t] = v;
    __syncthreads();
    for (int o = 1; o < 128; o <<= 1) {
        int a = (t >= o) ? sd[t - o] : 0;
        __syncthreads();
        sd[t] += a;
        __syncthreads();
    }
    if (t < NCH) sums[g * NCH + t] = sd[t] - v;
}

// scanC + fused rsqrt-degree computation (g==0 blocks do rn)
__global__ void k_scanC(int* __restrict__ off, const int* __restrict__ sums,
                        int* __restrict__ cur, const int* __restrict__ deg,
                        float* __restrict__ rnG, float* __restrict__ rnB) {
    int g = blockIdx.x / NCH, c = blockIdx.x % NCH;
    int i = c * 1024 + threadIdx.x;
    if (i < NN) {
        int o = off[g * (NN + 1) + i] + sums[g * NCH + c];
        off[g * (NN + 1) + i] = o;
        cur[g * NN + i] = o;
        if (g == 0) {
            int d0 = deg[i], d1 = deg[NN + i], d2 = deg[2 * NN + i];
            rnB[i]          = rsqrtf((float)max(d0, 1));
            rnB[NN + i]     = rsqrtf((float)max(d1, 1));
            rnB[2 * NN + i] = rsqrtf((float)max(d2, 1));
            rnG[i] = rsqrtf((float)max(d0 + d1 + d2, 1));
        }
    }
    if (i == NN - 1) off[g * (NN + 1) + NN] = (g < 3) ? E2 : E2G;
}

// ---- adjacency placement (branch + merged global) ----
__global__ void k_place(const int* __restrict__ eu, const int* __restrict__ ei,
                        int* __restrict__ cur, int* __restrict__ adj,
                        int* __restrict__ adjG) {
    int t = blockIdx.x * blockDim.x + threadIdx.x;
    if (t >= 3 * EE) return;
    int b = t / EE;
    int u = eu[t], it = NU + ei[t];
    int p = atomicAdd(&cur[b * NN + u], 1);
    adj[b * E2 + p] = it;
    int q = atomicAdd(&cur[b * NN + it], 1);
    adj[b * E2 + q] = u;
    int* curG = cur + 3 * NN;
    int pg = atomicAdd(&curG[u], 1);
    adjG[pg] = it;
    int qg = atomicAdd(&curG[it], 1);
    adjG[qg] = u;
}

__device__ __forceinline__ void accum8(int4 raw, float* __restrict__ acc) {
    __half2* h = (__half2*)&raw;
    #pragma unroll
    for (int k = 0; k < 4; k++) {
        float2 v = __half22float2(h[k]);
        acc[2 * k]     += v.x;
        acc[2 * k + 1] += v.y;
    }
}

__device__ __forceinline__ void accum8w(int4 raw, float w, float* __restrict__ acc) {
    __half2* h = (__half2*)&raw;
    #pragma unroll
    for (int k = 0; k < 4; k++) {
        float2 v = __half22float2(h[k]);
        acc[2 * k]     += w * v.x;
        acc[2 * k + 1] += w * v.y;
    }
}

// ---- group-per-node gather: 8 lanes own one node; 4 neighbors in flight ----
__device__ __forceinline__ void gathN(const __half* __restrict__ inp,
                                      const int* __restrict__ adj,
                                      int s, int e, int c,
                                      float* __restrict__ acc) {
    int j = s;
    for (; j + 4 <= e; j += 4) {
        int i0 = __ldg(adj + j),     i1 = __ldg(adj + j + 1);
        int i2 = __ldg(adj + j + 2), i3 = __ldg(adj + j + 3);
        int4 r0 = __ldg((const int4*)(inp + (size_t)i0 * DD + c * 8));
        int4 r1 = __ldg((const int4*)(inp + (size_t)i1 * DD + c * 8));
        int4 r2 = __ldg((const int4*)(inp + (size_t)i2 * DD + c * 8));
        int4 r3 = __ldg((const int4*)(inp + (size_t)i3 * DD + c * 8));
        accum8(r0, acc); accum8(r1, acc); accum8(r2, acc); accum8(r3, acc);
    }
    for (; j < e; j++) {
        int i0 = __ldg(adj + j);
        int4 r0 = __ldg((const int4*)(inp + (size_t)i0 * DD + c * 8));
        accum8(r0, acc);
    }
}

// weighted variant (w = rn[src])
__device__ __forceinline__ void gathNw(const __half* __restrict__ inp,
                                       const int* __restrict__ adj,
                                       int s, int e, const float* __restrict__ rn,
                                       int c, float* __restrict__ acc) {
    int j = s;
    for (; j + 4 <= e; j += 4) {
        int i0 = __ldg(adj + j),     i1 = __ldg(adj + j + 1);
        int i2 = __ldg(adj + j + 2), i3 = __ldg(adj + j + 3);
        float w0 = __ldg(rn + i0), w1 = __ldg(rn + i1);
        float w2 = __ldg(rn + i2), w3 = __ldg(rn + i3);
        int4 r0 = __ldg((const int4*)(inp + (size_t)i0 * DD + c * 8));
        int4 r1 = __ldg((const int4*)(inp + (size_t)i1 * DD + c * 8));
        int4 r2 = __ldg((const int4*)(inp + (size_t)i2 * DD + c * 8));
        int4 r3 = __ldg((const int4*)(inp + (size_t)i3 * DD + c * 8));
        accum8w(r0, w0, acc); accum8w(r1, w1, acc);
        accum8w(r2, w2, acc); accum8w(r3, w3, acc);
    }
    for (; j < e; j++) {
        int i0 = __ldg(adj + j);
        float w0 = __ldg(rn + i0);
        int4 r0 = __ldg((const int4*)(inp + (size_t)i0 * DD + c * 8));
        accum8w(r0, w0, acc);
    }
}

// store 8 dims (scaled) as fp16 int4 — every lane stores its chunk
__device__ __forceinline__ void store_h(__half* __restrict__ out, size_t n,
                                        int c, const float* __restrict__ acc,
                                        float scale) {
    __half2 h[4];
    #pragma unroll
    for (int k = 0; k < 4; k++)
        h[k] = __float22half2_rn(make_float2(acc[2 * k] * scale,
                                             acc[2 * k + 1] * scale));
    *(int4*)(out + n * DD + c * 8) = *(int4*)h;
}

// ---- global GCN layer 1: Z1 = rnG^2 * (Σ Z0[src])  (merged CSR) ----
__global__ void k_gL1(const __half* __restrict__ z0, __half* __restrict__ z1,
                      const int* __restrict__ offG, const int* __restrict__ adjG,
                      const float* __restrict__ rnG) {
    int t = blockIdx.x * blockDim.x + threadIdx.x;
    int n = t >> 3;
    if (n >= NN) return;
    int c = t & 7;
    float acc[8] = {0, 0, 0, 0, 0, 0, 0, 0};
    gathN(z0, adjG, offG[n], offG[n + 1], c, acc);
    float r = rnG[n];
    store_h(z1, n, c, acc, r * r);
}

// ---- global GCN L2 + combine: ALL = (z0/rn + z1/rn + rn*Σz1)/3 ----
__global__ void k_gL2c(const __half* __restrict__ z0, const __half* __restrict__ z1,
                       __half* __restrict__ allo, const int* __restrict__ offG,
                       const int* __restrict__ adjG, const float* __restrict__ rnG) {
    int t = blockIdx.x * blockDim.x + threadIdx.x;
    int n = t >> 3;
    if (n >= NN) return;
    int c = t & 7;
    float acc[8] = {0, 0, 0, 0, 0, 0, 0, 0};
    gathN(z1, adjG, offG[n], offG[n + 1], c, acc);
    float r = rnG[n];
    float inv = 1.0f / r;
    int4 ra = __ldg((const int4*)(z0 + (size_t)n * DD + c * 8));
    int4 rb = __ldg((const int4*)(z1 + (size_t)n * DD + c * 8));
    __half2* ha = (__half2*)&ra;
    __half2* hb = (__half2*)&rb;
    const float s3 = 1.0f / 3.0f;
    __half2 hout[4];
    #pragma unroll
    for (int k = 0; k < 4; k++) {
        float2 a = __half22float2(ha[k]);
        float2 b = __half22float2(hb[k]);
        hout[k] = __float22half2_rn(
            make_float2(((a.x + b.x) * inv + acc[2 * k] * r) * s3,
                        ((a.y + b.y) * inv + acc[2 * k + 1] * r) * s3));
    }
    *(int4*)(allo + (size_t)n * DD + c * 8) = *(int4*)hout;
}

// ---- branch layer 1: ZB_g = rnB_g(n)^2 * Σ rnB_g[src] * ALL[src] ----
__global__ void k_bL1(const __half* __restrict__ allo, __half* __restrict__ zb,
                      const int* __restrict__ off, const int* __restrict__ adj,
                      const float* __restrict__ rnB) {
    int t = blockIdx.x * blockDim.x + threadIdx.x;
    int q = t >> 3;
    if (q >= 3 * NN) return;
    int gg = q / NN, n = q - gg * NN;
    int c = t & 7;
    const float* rn = rnB + (size_t)gg * NN;
    float acc[8] = {0, 0, 0, 0, 0, 0, 0, 0};
    int s = off[gg * (NN + 1) + n], e = off[gg * (NN + 1) + n + 1];
    gathNw(allo, adj + (size_t)gg * E2, s, e, rn, c, acc);
    float r = rn[n];
    store_h(zb + (size_t)gg * NN * DD, n, c, acc, r * r);
}

// ---- branch L2 + combine + attention (users) / weighting (items) ----
__global__ void k_bL2f(const __half* __restrict__ allo, const __half* __restrict__ zb,
                       const int* __restrict__ off, const int* __restrict__ adj,
                       const float* __restrict__ rnB, const int* __restrict__ deg,
                       const float* __restrict__ W, float* __restrict__ au,
                       float* __restrict__ ifl) {
    int t = blockIdx.x * blockDim.x + threadIdx.x;
    int n = t >> 3;
    if (n >= NN) return;
    int c = t & 7;
    int4 ra = __ldg((const int4*)(allo + (size_t)n * DD + c * 8));
    __half2* ha = (__half2*)&ra;
    float f[3][8];
    const float s3 = 1.0f / 3.0f;
    #pragma unroll
    for (int gg = 0; gg < 3; gg++) {
        const __half* src = zb + (size_t)gg * NN * DD;
        float acc[8] = {0, 0, 0, 0, 0, 0, 0, 0};
        int s = off[gg * (NN + 1) + n], e = off[gg * (NN + 1) + n + 1];
        gathN(src, adj + (size_t)gg * E2, s, e, c, acc);
        float r = rnB[gg * NN + n];
        float inv = 1.0f / r;
        int4 rb = __ldg((const int4*)(src + (size_t)n * DD + c * 8));
        __half2* hb = (__half2*)&rb;
        #pragma unroll
        for (int k = 0; k < 4; k++) {
            float2 a = __half22float2(ha[k]);
            float2 b = __half22float2(hb[k]);   // zb row = rn * s1
            f[gg][2 * k]     = (a.x + b.x * inv + acc[2 * k] * r) * s3;
            f[gg][2 * k + 1] = (a.y + b.y * inv + acc[2 * k + 1] * r) * s3;
        }
    }
    if (n < NU) {
        // dots over 64 dims: per-lane partial (8 dims) + intra-group reduce (1,2,4)
        float s00 = 0, s01 = 0, s02 = 0, s11 = 0, s12 = 0, s22 = 0;
        #pragma unroll
        for (int k = 0; k < 8; k++) {
            s00 += f[0][k] * f[0][k];
            s01 += f[0][k] * f[1][k];
            s02 += f[0][k] * f[2][k];
            s11 += f[1][k] * f[1][k];
            s12 += f[1][k] * f[2][k];
            s22 += f[2][k] * f[2][k];
        }
        #pragma unroll
        for (int o = 1; o < 8; o <<= 1) {
            s00 += __shfl_xor_sync(0xffffffffu, s00, o);
            s01 += __shfl_xor_sync(0xffffffffu, s01, o);
            s02 += __shfl_xor_sync(0xffffffffu, s02, o);
            s11 += __shfl_xor_sync(0xffffffffu, s11, o);
            s12 += __shfl_xor_sync(0xffffffffu, s12, o);
            s22 += __shfl_xor_sync(0xffffffffu, s22, o);
        }
        float l0 = s02, l1 = s12, l2 = s22;
        float q0 = l0 * l0 / (l0 * l0 + 1e-12f);
        float q1 = l1 * l1 / (l1 * l1 + 1e-12f);
        float q2 = l2 * l2 / (l2 * l2 + 1e-12f);
        float c00 = s00 * q0, c01 = s01 * q1, c02 = s02 * q2;
        float c10 = s01 * q0, c11 = s11 * q1, c12 = s12 * q2;
        float r20 = c00 + c10 + l0;
        float r21 = c01 + c11 + l1;
        float r22 = c02 + c12 + l2;
        float att[3][3] = {{c00, c01, c02}, {c10, c11, c12}, {r20, r21, r22}};
        #pragma unroll
        for (int i = 0; i < 3; i++) {
            float m = fmaxf(att[i][0], fmaxf(att[i][1], att[i][2]));
            float e0 = expf((att[i][0] - m) * 0.125f);
            float e1 = expf((att[i][1] - m) * 0.125f);
            float e2 = expf((att[i][2] - m) * 0.125f);
            float inv = 1.0f / (e0 + e1 + e2);
            att[i][0] = e0 * inv; att[i][1] = e1 * inv; att[i][2] = e2 * inv;
        }
        float* base = au + (size_t)n * 192;   // [u][3][64]
        #pragma unroll
        for (int i = 0; i < 3; i++) {
            float4 o0, o1;
            o0.x = att[i][0] * f[0][0] + att[i][1] * f[1][0] + att[i][2] * f[2][0];
            o0.y = att[i][0] * f[0][1] + att[i][1] * f[1][1] + att[i][2] * f[2][1];
            o0.z = att[i][0] * f[0][2] + att[i][1] * f[1][2] + att[i][2] * f[2][2];
            o0.w = att[i][0] * f[0][3] + att[i][1] * f[1][3] + att[i][2] * f[2][3];
            o1.x = att[i][0] * f[0][4] + att[i][1] * f[1][4] + att[i][2] * f[2][4];
            o1.y = att[i][0] * f[0][5] + att[i][1] * f[1][5] + att[i][2] * f[2][5];
            o1.z = att[i][0] * f[0][6] + att[i][1] * f[1][6] + att[i][2] * f[2][6];
            o1.w = att[i][0] * f[0][7] + att[i][1] * f[1][7] + att[i][2] * f[2][7];
            *(float4*)(base + i * 64 + c * 8)     = o0;
            *(float4*)(base + i * 64 + c * 8 + 4) = o1;
        }
    } else {
        int i = n - NU;
        float w0 = (float)__ldg(deg + n)          * __ldg(W + 0);
        float w1 = (float)__ldg(deg + NN + n)     * __ldg(W + 1);
        float w2 = (float)__ldg(deg + 2 * NN + n) * __ldg(W + 2);
        float inv = 1.0f / (w0 + w1 + w2 + 1e-8f);
        w0 *= inv; w1 *= inv; w2 *= inv;
        float4 o0, o1;
        o0.x = f[0][0] * w0 + f[1][0] * w1 + f[2][0] * w2;
        o0.y = f[0][1] * w0 + f[1][1] * w1 + f[2][1] * w2;
        o0.z = f[0][2] * w0 + f[1][2] * w1 + f[2][2] * w2;
        o0.w = f[0][3] * w0 + f[1][3] * w1 + f[2][3] * w2;
        o1.x = f[0][4] * w0 + f[1][4] * w1 + f[2][4] * w2;
        o1.y = f[0][5] * w0 + f[1][5] * w1 + f[2][5] * w2;
        o1.z = f[0][6] * w0 + f[1][6] * w1 + f[2][6] * w2;
        o1.w = f[0][7] * w0 + f[1][7] * w1 + f[2][7] * w2;
        *(float4*)(ifl + (size_t)i * DD + c * 8)     = o0;
        *(float4*)(ifl + (size_t)i * DD + c * 8 + 4) = o1;
    }
}

// ---- BPR loss ----
__global__ void k_bpr(const int* __restrict__ batch, const float* __restrict__ au,
                      const float* __restrict__ ifl, float* __restrict__ acc) {
    int t = blockIdx.x * blockDim.x + threadIdx.x;
    int idx = t >> 5;
    if (idx >= NB * 3) return;
    int lane = t & 31;
    int n = idx / 3, b = idx % 3;
    const int* bd = batch + n * 9 + b * 3;
    int u = bd[0], pos = bd[1], neg = bd[2];
    float2 uf = *(const float2*)(au + (size_t)u * 192 + b * 64 + 2 * lane);
    float2 p  = *(const float2*)(ifl + (size_t)pos * DD + 2 * lane);
    float2 q  = *(const float2*)(ifl + (size_t)neg * DD + 2 * lane);
    float s = uf.x * (p.x - q.x) + uf.y * (p.y - q.y);
    #pragma unroll
    for (int o = 16; o; o >>= 1) s += __shfl_xor_sync(0xffffffffu, s, o);
    if (lane == 0) {
        float sig = 1.0f / (1.0f + expf(-s));
        atomicAdd(acc, -logf(1e-10f + sig) * (1.0f / (float)NB));
    }
}

// ---- fused sum-of-squares over both embedding tables ----
__global__ void k_sumsq2(const float* __restrict__ ue, const float* __restrict__ ie,
                         float* __restrict__ acc) {
    const int NUE = NU * DD, NIE = NI * DD;
    float su = 0.0f, si = 0.0f;
    for (int i = blockIdx.x * blockDim.x + threadIdx.x; i < NUE + NIE;
         i += gridDim.x * blockDim.x) {
        if (i < NUE) { float v = ue[i]; su += v * v; }
        else         { float v = ie[i - NUE]; si += v * v; }
    }
    #pragma unroll
    for (int o = 16; o; o >>= 1) {
        su += __shfl_xor_sync(0xffffffffu, su, o);
        si += __shfl_xor_sync(0xffffffffu, si, o);
    }
    if ((threadIdx.x & 31) == 0) {
        if (su != 0.0f) atomicAdd(acc + 1, su);
        if (si != 0.0f) atomicAdd(acc + 2, si);
    }
}

__global__ void k_final(const float* __restrict__ acc, float* __restrict__ out) {
    out[0] = acc[0] + 0.001f * (sqrtf(acc[1]) + sqrtf(acc[2])) / 40001.0f;
}

extern "C" void kernel_launch(void* const* d_in, const int* in_sizes, int n_in,
                              void* d_out, int out_size) {
    const float* user_emb = (const float*)d_in[0];
    const float* item_emb = (const float*)d_in[1];
    const float* W        = (const float*)d_in[2];
    const int*   eu       = (const int*)d_in[3];
    const int*   ei       = (const int*)d_in[4];
    const int*   batch    = (const int*)d_in[5];
    float* out = (float*)d_out;

    __half *Z0, *Z1, *ALLh, *ZB;
    float *AU, *IF, *rnG, *rnB, *ACC;
    int *adj, *adjG, *deg, *off, *cur, *sums;
    cudaGetSymbolAddress((void**)&Z0,   d_Z0);
    cudaGetSymbolAddress((void**)&Z1,   d_Z1);
    cudaGetSymbolAddress((void**)&ALLh, d_ALLh);
    cudaGetSymbolAddress((void**)&ZB,   d_ZB);
    cudaGetSymbolAddress((void**)&AU,   d_AU);
    cudaGetSymbolAddress((void**)&IF,   d_IF);
    cudaGetSymbolAddress((void**)&rnG,  d_rnG);
    cudaGetSymbolAddress((void**)&rnB,  d_rnB);
    cudaGetSymbolAddress((void**)&ACC,  d_ACC);
    cudaGetSymbolAddress((void**)&adj,  d_adj);
    cudaGetSymbolAddress((void**)&adjG, d_adjG);
    cudaGetSymbolAddress((void**)&deg,  d_deg);
    cudaGetSymbolAddress((void**)&off,  d_off);
    cudaGetSymbolAddress((void**)&cur,  d_cur);
    cudaGetSymbolAddress((void**)&sums, d_sums);

    const int NTH = 256;
    auto blocksFor = [](long threads) { return (int)((threads + 255) / 256); };
    const int* offG = off + 3 * (NN + 1);

    // ---- CSR build (branch + merged global) ----
    cudaMemsetAsync(deg, 0, 3 * NN * sizeof(int));
    k_degcnt<<<blocksFor(3L * EE), NTH>>>(eu, ei, deg);
    k_scanA<<<4 * NCH, 1024>>>(deg, off, sums);
    k_scanB<<<4, 128>>>(sums);
    k_scanC<<<4 * NCH, 1024>>>(off, sums, cur, deg, rnG, rnB);
    k_place<<<blocksFor(3L * EE), NTH>>>(eu, ei, cur, adj, adjG);

    // Z0 = rnG * concat(user_emb, item_emb)
    k_conv<<<blocksFor((long)NN * DD / 2), NTH>>>(user_emb, item_emb, rnG, Z0);

    // ---- global LightGCN (merged CSR, group-per-node) ----
    k_gL1<<<blocksFor((long)NN * 8), NTH>>>(Z0, Z1, offG, adjG, rnG);
    k_gL2c<<<blocksFor((long)NN * 8), NTH>>>(Z0, Z1, ALLh, offG, adjG, rnG);

    // ---- branch LightGCNs ----
    k_bL1<<<blocksFor(3L * NN * 8), NTH>>>(ALLh, ZB, off, adj, rnB);
    k_bL2f<<<blocksFor((long)NN * 8), NTH>>>(ALLh, ZB, off, adj, rnB, deg, W, AU, IF);

    // ---- losses ----
    cudaMemsetAsync(ACC, 0, 4 * sizeof(float));
    k_bpr<<<blocksFor((long)NB * 3 * 32), NTH>>>(batch, AU, IF, ACC);
    k_sumsq2<<<512, NTH>>>(user_emb, item_emb, ACC);
    k_final<<<1, 1>>>(ACC, out);
}

// round 10
// speedup vs baseline: 1.0600x; 1.0600x over previous
#include <cuda_runtime.h>
#include <cuda_fp16.h>
#include <math.h>

#define NU 60001
#define NI 40001
#define NN 100002
#define DD 64
#define EE 600000
#define E2 (2*EE)
#define E2G (3*E2)
#define NB 2048
#define NCH 98   // ceil(NN/1024)

// ---- static device scratch ----
__device__ __align__(128) __half d_Z0 [NN * DD];      // rnG-scaled x0
__device__ __align__(128) __half d_Z1 [NN * DD];      // rnG^2 * s1
__device__ __align__(128) __half d_ALLh[NN * DD];     // plain ALL (shared hot gather src)
__device__ __align__(128) __half d_ZB [3 * NN * DD];  // rnB_g * s1_g (pre-scaled)
__device__ __align__(128) float  d_AU [NU * 3 * DD];  // all_user [u][3][64]
__device__ __align__(128) float  d_IF [NI * DD];      // item_final [i][64]
__device__ __align__(128) int    d_adj [3 * E2];      // branch adjacency
__device__ __align__(128) int    d_adjG[E2G];         // merged global adjacency
__device__ __align__(128) int    d_deg [3 * NN];
__device__ __align__(128) int    d_off [4 * (NN + 1)];  // 3 branches + global
__device__ __align__(128) int    d_cur [4 * NN];
__device__ __align__(128) int    d_sums[4 * NCH];
__device__ __align__(128) float  d_rnG [NN];
__device__ __align__(128) float  d_rnB [3 * NN];
__device__ float d_ACC[4];

// ---- convert inputs to fp16, pre-scaled by rnG ----
__global__ void k_conv(const float* __restrict__ ue, const float* __restrict__ ie,
                       const float* __restrict__ rnG, __half* __restrict__ z0) {
    int i = blockIdx.x * blockDim.x + threadIdx.x;       // half2 index
    if (i >= NN * DD / 2) return;
    int elem = i * 2;
    int n = i >> 5;
    const int UB = NU * DD;
    float2 v = (elem < UB) ? __ldg((const float2*)(ue + elem))
                           : __ldg((const float2*)(ie + (elem - UB)));
    float r = __ldg(rnG + n);
    ((__half2*)z0)[i] = __float22half2_rn(make_float2(v.x * r, v.y * r));
}

// ---- degree count ----
__global__ void k_degcnt(const int* __restrict__ eu, const int* __restrict__ ei,
                         int* __restrict__ deg) {
    int t = blockIdx.x * blockDim.x + threadIdx.x;
    if (t >= 3 * EE) return;
    int b = t / EE;
    atomicAdd(&deg[b * NN + eu[t]], 1);
    atomicAdd(&deg[b * NN + NU + ei[t]], 1);
}

// ---- 3-pass exclusive scan over 4 graphs (3 branch + merged global) ----
__global__ void k_scanA(const int* __restrict__ deg, int* __restrict__ off,
                        int* __restrict__ sums) {
    int g = blockIdx.x / NCH, c = blockIdx.x % NCH;
    int i = c * 1024 + threadIdx.x;
    int v = 0;
    if (i < NN)
        v = (g < 3) ? deg[g * NN + i]
                    : deg[i] + deg[NN + i] + deg[2 * NN + i];
    __shared__ int sd[1024];
    sd[threadIdx.x] = v;
    __syncthreads();
    for (int o = 1; o < 1024; o <<= 1) {
        int a = (threadIdx.x >= o) ? sd[threadIdx.x - o] : 0;
        __syncthreads();
        sd[threadIdx.x] += a;
        __syncthreads();
    }
    int inc = sd[threadIdx.x];
    if (i < NN) off[g * (NN + 1) + i] = inc - v;
    if (threadIdx.x == 1023) sums[g * NCH + c] = inc;
}

__global__ void k_scanB(int* __restrict__ sums) {
    int g = blockIdx.x, t = threadIdx.x;
    __shared__ int sd[128];
    int v = (t < NCH) ? sums[g * NCH + t] : 0;
    sd[t] = v;
    __syncthreads();
    for (int o = 1; o < 128; o <<= 1) {
        int a = (t >= o) ? sd[t - o] : 0;
        __syncthreads();
        sd[t] += a;
        __syncthreads();
    }
    if (t < NCH) sums[g * NCH + t] = sd[t] - v;
}

// scanC + fused rsqrt-degree computation (g==0 blocks do rn)
__global__ void k_scanC(int* __restrict__ off, const int* __restrict__ sums,
                        int* __restrict__ cur, const int* __restrict__ deg,
                        float* __restrict__ rnG, float* __restrict__ rnB) {
    int g = blockIdx.x / NCH, c = blockIdx.x % NCH;
    int i = c * 1024 + threadIdx.x;
    if (i < NN) {
        int o = off[g * (NN + 1) + i] + sums[g * NCH + c];
        off[g * (NN + 1) + i] = o;
        cur[g * NN + i] = o;
        if (g == 0) {
            int d0 = deg[i], d1 = deg[NN + i], d2 = deg[2 * NN + i];
            rnB[i]          = rsqrtf((float)max(d0, 1));
            rnB[NN + i]     = rsqrtf((float)max(d1, 1));
            rnB[2 * NN + i] = rsqrtf((float)max(d2, 1));
            rnG[i] = rsqrtf((float)max(d0 + d1 + d2, 1));
        }
    }
    if (i == NN - 1) off[g * (NN + 1) + NN] = (g < 3) ? E2 : E2G;
}

// ---- adjacency placement (branch + merged global) ----
__global__ void k_place(const int* __restrict__ eu, const int* __restrict__ ei,
                        int* __restrict__ cur, int* __restrict__ adj,
                        int* __restrict__ adjG) {
    int t = blockIdx.x * blockDim.x + threadIdx.x;
    if (t >= 3 * EE) return;
    int b = t / EE;
    int u = eu[t], it = NU + ei[t];
    int p = atomicAdd(&cur[b * NN + u], 1);
    adj[b * E2 + p] = it;
    int q = atomicAdd(&cur[b * NN + it], 1);
    adj[b * E2 + q] = u;
    int* curG = cur + 3 * NN;
    int pg = atomicAdd(&curG[u], 1);
    adjG[pg] = it;
    int qg = atomicAdd(&curG[it], 1);
    adjG[qg] = u;
}

__device__ __forceinline__ void accum8(int4 raw, float* __restrict__ acc) {
    __half2* h = (__half2*)&raw;
    #pragma unroll
    for (int k = 0; k < 4; k++) {
        float2 v = __half22float2(h[k]);
        acc[2 * k]     += v.x;
        acc[2 * k + 1] += v.y;
    }
}

__device__ __forceinline__ void accum8w(int4 raw, float w, float* __restrict__ acc) {
    __half2* h = (__half2*)&raw;
    #pragma unroll
    for (int k = 0; k < 4; k++) {
        float2 v = __half22float2(h[k]);
        acc[2 * k]     += w * v.x;
        acc[2 * k + 1] += w * v.y;
    }
}

// ---- warp-per-node gather: 4 lane-groups split the SAME node's neighbors.
//      Group g handles neighbors s+g, s+g+4, ... ; up to 4 in flight (stride 16).
__device__ __forceinline__ void gath4(const __half* __restrict__ inp,
                                      const int* __restrict__ adj,
                                      int s, int e, int g, int c,
                                      float* __restrict__ acc) {
    int j = s + g;
    for (; j + 12 < e; j += 16) {
        int i0 = __ldg(adj + j);
        int i1 = __ldg(adj + j + 4);
        int i2 = __ldg(adj + j + 8);
        int i3 = __ldg(adj + j + 12);
        int4 r0 = __ldg((const int4*)(inp + (size_t)i0 * DD + c * 8));
        int4 r1 = __ldg((const int4*)(inp + (size_t)i1 * DD + c * 8));
        int4 r2 = __ldg((const int4*)(inp + (size_t)i2 * DD + c * 8));
        int4 r3 = __ldg((const int4*)(inp + (size_t)i3 * DD + c * 8));
        accum8(r0, acc); accum8(r1, acc); accum8(r2, acc); accum8(r3, acc);
    }
    for (; j < e; j += 4) {
        int i0 = __ldg(adj + j);
        int4 r0 = __ldg((const int4*)(inp + (size_t)i0 * DD + c * 8));
        accum8(r0, acc);
    }
}

// weighted variant (w = rn[src])
__device__ __forceinline__ void gath4w(const __half* __restrict__ inp,
                                       const int* __restrict__ adj,
                                       int s, int e, const float* __restrict__ rn,
                                       int g, int c, float* __restrict__ acc) {
    int j = s + g;
    for (; j + 12 < e; j += 16) {
        int i0 = __ldg(adj + j);
        int i1 = __ldg(adj + j + 4);
        int i2 = __ldg(adj + j + 8);
        int i3 = __ldg(adj + j + 12);
        float w0 = __ldg(rn + i0), w1 = __ldg(rn + i1);
        float w2 = __ldg(rn + i2), w3 = __ldg(rn + i3);
        int4 r0 = __ldg((const int4*)(inp + (size_t)i0 * DD + c * 8));
        int4 r1 = __ldg((const int4*)(inp + (size_t)i1 * DD + c * 8));
        int4 r2 = __ldg((const int4*)(inp + (size_t)i2 * DD + c * 8));
        int4 r3 = __ldg((const int4*)(inp + (size_t)i3 * DD + c * 8));
        accum8w(r0, w0, acc); accum8w(r1, w1, acc);
        accum8w(r2, w2, acc); accum8w(r3, w3, acc);
    }
    for (; j < e; j += 4) {
        int i0 = __ldg(adj + j);
        float w0 = __ldg(rn + i0);
        int4 r0 = __ldg((const int4*)(inp + (size_t)i0 * DD + c * 8));
        accum8w(r0, w0, acc);
    }
}

// butterfly-reduce acc[8] across the 4 lane groups
__device__ __forceinline__ void red4(float* __restrict__ acc) {
    #pragma unroll
    for (int k = 0; k < 8; k++) {
        acc[k] += __shfl_xor_sync(0xffffffffu, acc[k], 8);
        acc[k] += __shfl_xor_sync(0xffffffffu, acc[k], 16);
    }
}

// lanes g==0 store 8 dims (scaled) as fp16 int4
__device__ __forceinline__ void store_h(__half* __restrict__ out, size_t n,
                                        int g, int c, const float* __restrict__ acc,
                                        float scale) {
    if (g == 0) {
        __half2 h[4];
        #pragma unroll
        for (int k = 0; k < 4; k++)
            h[k] = __float22half2_rn(make_float2(acc[2 * k] * scale,
                                                 acc[2 * k + 1] * scale));
        *(int4*)(out + n * DD + c * 8) = *(int4*)h;
    }
}

// ---- global GCN layer 1: Z1 = rnG^2 * (Σ Z0[src])  (merged CSR) ----
__global__ void k_gL1(const __half* __restrict__ z0, __half* __restrict__ z1,
                      const int* __restrict__ offG, const int* __restrict__ adjG,
                      const float* __restrict__ rnG) {
    int t = blockIdx.x * blockDim.x + threadIdx.x;
    int n = t >> 5;
    if (n >= NN) return;
    int lane = t & 31, g = lane >> 3, c = lane & 7;
    float acc[8] = {0, 0, 0, 0, 0, 0, 0, 0};
    gath4(z0, adjG, offG[n], offG[n + 1], g, c, acc);
    red4(acc);
    float r = rnG[n];
    store_h(z1, n, g, c, acc, r * r);
}

// ---- global GCN L2 + combine: ALL = (z0/rn + z1/rn + rn*Σz1)/3 ----
__global__ void k_gL2c(const __half* __restrict__ z0, const __half* __restrict__ z1,
                       __half* __restrict__ allo, const int* __restrict__ offG,
                       const int* __restrict__ adjG, const float* __restrict__ rnG) {
    int t = blockIdx.x * blockDim.x + threadIdx.x;
    int n = t >> 5;
    if (n >= NN) return;
    int lane = t & 31, g = lane >> 3, c = lane & 7;
    float acc[8] = {0, 0, 0, 0, 0, 0, 0, 0};
    gath4(z1, adjG, offG[n], offG[n + 1], g, c, acc);
    red4(acc);
    if (g == 0) {
        float r = rnG[n];
        float inv = 1.0f / r;
        int4 ra = __ldg((const int4*)(z0 + (size_t)n * DD + c * 8));
        int4 rb = __ldg((const int4*)(z1 + (size_t)n * DD + c * 8));
        __half2* ha = (__half2*)&ra;
        __half2* hb = (__half2*)&rb;
        const float s3 = 1.0f / 3.0f;
        __half2 hout[4];
        #pragma unroll
        for (int k = 0; k < 4; k++) {
            float2 a = __half22float2(ha[k]);
            float2 b = __half22float2(hb[k]);
            hout[k] = __float22half2_rn(
                make_float2(((a.x + b.x) * inv + acc[2 * k] * r) * s3,
                            ((a.y + b.y) * inv + acc[2 * k + 1] * r) * s3));
        }
        *(int4*)(allo + (size_t)n * DD + c * 8) = *(int4*)hout;
    }
}

// ---- branch layer 1: ZB_g = rnB_g(n)^2 * Σ rnB_g[src] * ALL[src] ----
__global__ void k_bL1(const __half* __restrict__ allo, __half* __restrict__ zb,
                      const int* __restrict__ off, const int* __restrict__ adj,
                      const float* __restrict__ rnB) {
    int t = blockIdx.x * blockDim.x + threadIdx.x;
    int q = t >> 5;
    if (q >= 3 * NN) return;
    int gg = q / NN, n = q - gg * NN;
    int lane = t & 31, g = lane >> 3, c = lane & 7;
    const float* rn = rnB + (size_t)gg * NN;
    float acc[8] = {0, 0, 0, 0, 0, 0, 0, 0};
    int s = off[gg * (NN + 1) + n], e = off[gg * (NN + 1) + n + 1];
    gath4w(allo, adj + (size_t)gg * E2, s, e, rn, g, c, acc);
    red4(acc);
    float r = rn[n];
    store_h(zb + (size_t)gg * NN * DD, n, g, c, acc, r * r);
}

// ---- branch L2 + combine + attention (users) / weighting (items) ----
__global__ void k_bL2f(const __half* __restrict__ allo, const __half* __restrict__ zb,
                       const int* __restrict__ off, const int* __restrict__ adj,
                       const float* __restrict__ rnB, const int* __restrict__ deg,
                       const float* __restrict__ W, float* __restrict__ au,
                       float* __restrict__ ifl) {
    int t = blockIdx.x * blockDim.x + threadIdx.x;
    int n = t >> 5;
    if (n >= NN) return;
    int lane = t & 31, g = lane >> 3, c = lane & 7;
    int4 ra = __ldg((const int4*)(allo + (size_t)n * DD + c * 8));
    __half2* ha = (__half2*)&ra;
    float f[3][8];
    const float s3 = 1.0f / 3.0f;
    #pragma unroll
    for (int gg = 0; gg < 3; gg++) {
        const __half* src = zb + (size_t)gg * NN * DD;
        float acc[8] = {0, 0, 0, 0, 0, 0, 0, 0};
        int s = off[gg * (NN + 1) + n], e = off[gg * (NN + 1) + n + 1];
        gath4(src, adj + (size_t)gg * E2, s, e, g, c, acc);
        red4(acc);
        float r = rnB[gg * NN + n];
        float inv = 1.0f / r;
        int4 rb = __ldg((const int4*)(src + (size_t)n * DD + c * 8));
        __half2* hb = (__half2*)&rb;
        #pragma unroll
        for (int k = 0; k < 4; k++) {
            float2 a = __half22float2(ha[k]);
            float2 b = __half22float2(hb[k]);   // zb row = rn * s1
            f[gg][2 * k]     = (a.x + b.x * inv + acc[2 * k] * r) * s3;
            f[gg][2 * k + 1] = (a.y + b.y * inv + acc[2 * k + 1] * r) * s3;
        }
    }
    if (n < NU) {
        float s00 = 0, s01 = 0, s02 = 0, s11 = 0, s12 = 0, s22 = 0;
        #pragma unroll
        for (int k = 0; k < 8; k++) {
            s00 += f[0][k] * f[0][k];
            s01 += f[0][k] * f[1][k];
            s02 += f[0][k] * f[2][k];
            s11 += f[1][k] * f[1][k];
            s12 += f[1][k] * f[2][k];
            s22 += f[2][k] * f[2][k];
        }
        #pragma unroll
        for (int o = 1; o < 8; o <<= 1) {
            s00 += __shfl_xor_sync(0xffffffffu, s00, o);
            s01 += __shfl_xor_sync(0xffffffffu, s01, o);
            s02 += __shfl_xor_sync(0xffffffffu, s02, o);
            s11 += __shfl_xor_sync(0xffffffffu, s11, o);
            s12 += __shfl_xor_sync(0xffffffffu, s12, o);
            s22 += __shfl_xor_sync(0xffffffffu, s22, o);
        }
        float l0 = s02, l1 = s12, l2 = s22;
        float q0 = l0 * l0 / (l0 * l0 + 1e-12f);
        float q1 = l1 * l1 / (l1 * l1 + 1e-12f);
        float q2 = l2 * l2 / (l2 * l2 + 1e-12f);
        float c00 = s00 * q0, c01 = s01 * q1, c02 = s02 * q2;
        float c10 = s01 * q0, c11 = s11 * q1, c12 = s12 * q2;
        float r20 = c00 + c10 + l0;
        float r21 = c01 + c11 + l1;
        float r22 = c02 + c12 + l2;
        float att[3][3] = {{c00, c01, c02}, {c10, c11, c12}, {r20, r21, r22}};
        #pragma unroll
        for (int i = 0; i < 3; i++) {
            float m = fmaxf(att[i][0], fmaxf(att[i][1], att[i][2]));
            float e0 = expf((att[i][0] - m) * 0.125f);
            float e1 = expf((att[i][1] - m) * 0.125f);
            float e2 = expf((att[i][2] - m) * 0.125f);
            float inv = 1.0f / (e0 + e1 + e2);
            att[i][0] = e0 * inv; att[i][1] = e1 * inv; att[i][2] = e2 * inv;
        }
        if (g == 0) {
            float* base = au + (size_t)n * 192;   // [u][3][64]
            #pragma unroll
            for (int i = 0; i < 3; i++) {
                float4 o0, o1;
                o0.x = att[i][0] * f[0][0] + att[i][1] * f[1][0] + att[i][2] * f[2][0];
                o0.y = att[i][0] * f[0][1] + att[i][1] * f[1][1] + att[i][2] * f[2][1];
                o0.z = att[i][0] * f[0][2] + att[i][1] * f[1][2] + att[i][2] * f[2][2];
                o0.w = att[i][0] * f[0][3] + att[i][1] * f[1][3] + att[i][2] * f[2][3];
                o1.x = att[i][0] * f[0][4] + att[i][1] * f[1][4] + att[i][2] * f[2][4];
                o1.y = att[i][0] * f[0][5] + att[i][1] * f[1][5] + att[i][2] * f[2][5];
                o1.z = att[i][0] * f[0][6] + att[i][1] * f[1][6] + att[i][2] * f[2][6];
                o1.w = att[i][0] * f[0][7] + att[i][1] * f[1][7] + att[i][2] * f[2][7];
                *(float4*)(base + i * 64 + c * 8)     = o0;
                *(float4*)(base + i * 64 + c * 8 + 4) = o1;
            }
        }
    } else {
        if (g == 0) {
            int i = n - NU;
            float w0 = (float)__ldg(deg + n)          * __ldg(W + 0);
            float w1 = (float)__ldg(deg + NN + n)     * __ldg(W + 1);
            float w2 = (float)__ldg(deg + 2 * NN + n) * __ldg(W + 2);
            float inv = 1.0f / (w0 + w1 + w2 + 1e-8f);
            w0 *= inv; w1 *= inv; w2 *= inv;
            float4 o0, o1;
            o0.x = f[0][0] * w0 + f[1][0] * w1 + f[2][0] * w2;
            o0.y = f[0][1] * w0 + f[1][1] * w1 + f[2][1] * w2;
            o0.z = f[0][2] * w0 + f[1][2] * w1 + f[2][2] * w2;
            o0.w = f[0][3] * w0 + f[1][3] * w1 + f[2][3] * w2;
            o1.x = f[0][4] * w0 + f[1][4] * w1 + f[2][4] * w2;
            o1.y = f[0][5] * w0 + f[1][5] * w1 + f[2][5] * w2;
            o1.z = f[0][6] * w0 + f[1][6] * w1 + f[2][6] * w2;
            o1.w = f[0][7] * w0 + f[1][7] * w1 + f[2][7] * w2;
            *(float4*)(ifl + (size_t)i * DD + c * 8)     = o0;
            *(float4*)(ifl + (size_t)i * DD + c * 8 + 4) = o1;
        }
    }
}

// ---- BPR loss ----
__global__ void k_bpr(const int* __restrict__ batch, const float* __restrict__ au,
                      const float* __restrict__ ifl, float* __restrict__ acc) {
    int t = blockIdx.x * blockDim.x + threadIdx.x;
    int idx = t >> 5;
    if (idx >= NB * 3) return;
    int lane = t & 31;
    int n = idx / 3, b = idx % 3;
    const int* bd = batch + n * 9 + b * 3;
    int u = bd[0], pos = bd[1], neg = bd[2];
    float2 uf = *(const float2*)(au + (size_t)u * 192 + b * 64 + 2 * lane);
    float2 p  = *(const float2*)(ifl + (size_t)pos * DD + 2 * lane);
    float2 q  = *(const float2*)(ifl + (size_t)neg * DD + 2 * lane);
    float s = uf.x * (p.x - q.x) + uf.y * (p.y - q.y);
    #pragma unroll
    for (int o = 16; o; o >>= 1) s += __shfl_xor_sync(0xffffffffu, s, o);
    if (lane == 0) {
        float sig = 1.0f / (1.0f + expf(-s));
        atomicAdd(acc, -logf(1e-10f + sig) * (1.0f / (float)NB));
    }
}

// ---- fused sum-of-squares over both embedding tables ----
__global__ void k_sumsq2(const float* __restrict__ ue, const float* __restrict__ ie,
                         float* __restrict__ acc) {
    const int NUE = NU * DD, NIE = NI * DD;
    float su = 0.0f, si = 0.0f;
    for (int i = blockIdx.x * blockDim.x + threadIdx.x; i < NUE + NIE;
         i += gridDim.x * blockDim.x) {
        if (i < NUE) { float v = ue[i]; su += v * v; }
        else         { float v = ie[i - NUE]; si += v * v; }
    }
    #pragma unroll
    for (int o = 16; o; o >>= 1) {
        su += __shfl_xor_sync(0xffffffffu, su, o);
        si += __shfl_xor_sync(0xffffffffu, si, o);
    }
    if ((threadIdx.x & 31) == 0) {
        if (su != 0.0f) atomicAdd(acc + 1, su);
        if (si != 0.0f) atomicAdd(acc + 2, si);
    }
}

__global__ void k_final(const float* __restrict__ acc, float* __restrict__ out) {
    out[0] = acc[0] + 0.001f * (sqrtf(acc[1]) + sqrtf(acc[2])) / 40001.0f;
}

extern "C" void kernel_launch(void* const* d_in, const int* in_sizes, int n_in,
                              void* d_out, int out_size) {
    const float* user_emb = (const float*)d_in[0];
    const float* item_emb = (const float*)d_in[1];
    const float* W        = (const float*)d_in[2];
    const int*   eu       = (const int*)d_in[3];
    const int*   ei       = (const int*)d_in[4];
    const int*   batch    = (const int*)d_in[5];
    float* out = (float*)d_out;

    __half *Z0, *Z1, *ALLh, *ZB;
    float *AU, *IF, *rnG, *rnB, *ACC;
    int *adj, *adjG, *deg, *off, *cur, *sums;
    cudaGetSymbolAddress((void**)&Z0,   d_Z0);
    cudaGetSymbolAddress((void**)&Z1,   d_Z1);
    cudaGetSymbolAddress((void**)&ALLh, d_ALLh);
    cudaGetSymbolAddress((void**)&ZB,   d_ZB);
    cudaGetSymbolAddress((void**)&AU,   d_AU);
    cudaGetSymbolAddress((void**)&IF,   d_IF);
    cudaGetSymbolAddress((void**)&rnG,  d_rnG);
    cudaGetSymbolAddress((void**)&rnB,  d_rnB);
    cudaGetSymbolAddress((void**)&ACC,  d_ACC);
    cudaGetSymbolAddress((void**)&adj,  d_adj);
    cudaGetSymbolAddress((void**)&adjG, d_adjG);
    cudaGetSymbolAddress((void**)&deg,  d_deg);
    cudaGetSymbolAddress((void**)&off,  d_off);
    cudaGetSymbolAddress((void**)&cur,  d_cur);
    cudaGetSymbolAddress((void**)&sums, d_sums);

    const int NTH = 256;
    auto blocksFor = [](long threads) { return (int)((threads + 255) / 256); };
    const int* offG = off + 3 * (NN + 1);

    // ---- CSR build (branch + merged global) ----
    cudaMemsetAsync(deg, 0, 3 * NN * sizeof(int));
    k_degcnt<<<blocksFor(3L * EE), NTH>>>(eu, ei, deg);
    k_scanA<<<4 * NCH, 1024>>>(deg, off, sums);
    k_scanB<<<4, 128>>>(sums);
    k_scanC<<<4 * NCH, 1024>>>(off, sums, cur, deg, rnG, rnB);
    k_place<<<blocksFor(3L * EE), NTH>>>(eu, ei, cur, adj, adjG);

    // Z0 = rnG * concat(user_emb, item_emb)
    k_conv<<<blocksFor((long)NN * DD / 2), NTH>>>(user_emb, item_emb, rnG, Z0);

    // ---- global LightGCN (merged CSR, warp-per-node) ----
    k_gL1<<<blocksFor((long)NN * 32), NTH>>>(Z0, Z1, offG, adjG, rnG);
    k_gL2c<<<blocksFor((long)NN * 32), NTH>>>(Z0, Z1, ALLh, offG, adjG, rnG);

    // ---- branch LightGCNs ----
    k_bL1<<<blocksFor(3L * NN * 32), NTH>>>(ALLh, ZB, off, adj, rnB);
    k_bL2f<<<blocksFor((long)NN * 32), NTH>>>(ALLh, ZB, off, adj, rnB, deg, W, AU, IF);

    // ---- losses ----
    cudaMemsetAsync(ACC, 0, 4 * sizeof(float));
    k_bpr<<<blocksFor((long)NB * 3 * 32), NTH>>>(batch, AU, IF, ACC);
    k_sumsq2<<<512, NTH>>>(user_emb, item_emb, ACC);
    k_final<<<1, 1>>>(ACC, out);
}

// round 11
// speedup vs baseline: 1.1649x; 1.0990x over previous
#include <cuda_runtime.h>
#include <cuda_fp16.h>
#include <math.h>

#define NU 60001
#define NI 40001
#define NN 100002
#define DD 64
#define EE 600000
#define E2 (2*EE)
#define NB 2048
#define NCH 98   // ceil(NN/1024)

// ---- static device scratch ----
__device__ __align__(128) __half d_Z0 [NN * DD];      // rnG-scaled x0
__device__ __align__(128) __half d_Z1 [NN * DD];      // rnG^2 * s1
__device__ __align__(128) __half d_ALLh[NN * DD];     // plain ALL (shared hot gather src)
__device__ __align__(128) __half d_ZB [3 * NN * DD];  // rnB_g * s1_g (pre-scaled)
__device__ __align__(128) float  d_AU [NU * 3 * DD];  // all_user [u][3][64]
__device__ __align__(128) float  d_IF [NI * DD];      // item_final [i][64]
__device__ __align__(128) int    d_adj [3 * E2];
__device__ __align__(128) int    d_deg [3 * NN];
__device__ __align__(128) int    d_off [3 * (NN + 1)];
__device__ __align__(128) int    d_cur [3 * NN];
__device__ __align__(128) int    d_sums[3 * NCH];
__device__ __align__(128) float  d_rnG [NN];
__device__ __align__(128) float  d_rnB [3 * NN];
__device__ float d_ACC[4];

// ---- convert inputs to fp16, pre-scaled by rnG ----
__global__ void k_conv(const float* __restrict__ ue, const float* __restrict__ ie,
                       const float* __restrict__ rnG, __half* __restrict__ z0) {
    int i = blockIdx.x * blockDim.x + threadIdx.x;       // half2 index
    if (i >= NN * DD / 2) return;
    int elem = i * 2;
    int n = i >> 5;
    const int UB = NU * DD;
    float2 v = (elem < UB) ? __ldg((const float2*)(ue + elem))
                           : __ldg((const float2*)(ie + (elem - UB)));
    float r = __ldg(rnG + n);
    ((__half2*)z0)[i] = __float22half2_rn(make_float2(v.x * r, v.y * r));
}

// ---- degree count ----
__global__ void k_degcnt(const int* __restrict__ eu, const int* __restrict__ ei,
                         int* __restrict__ deg) {
    int t = blockIdx.x * blockDim.x + threadIdx.x;
    if (t >= 3 * EE) return;
    int b = t / EE;
    atomicAdd(&deg[b * NN + eu[t]], 1);
    atomicAdd(&deg[b * NN + NU + ei[t]], 1);
}

// ---- 3-pass exclusive scan ----
__global__ void k_scanA(const int* __restrict__ deg, int* __restrict__ off,
                        int* __restrict__ sums) {
    int g = blockIdx.x / NCH, c = blockIdx.x % NCH;
    int i = c * 1024 + threadIdx.x;
    int v = (i < NN) ? deg[g * NN + i] : 0;
    __shared__ int sd[1024];
    sd[threadIdx.x] = v;
    __syncthreads();
    for (int o = 1; o < 1024; o <<= 1) {
        int a = (threadIdx.x >= o) ? sd[threadIdx.x - o] : 0;
        __syncthreads();
        sd[threadIdx.x] += a;
        __syncthreads();
    }
    int inc = sd[threadIdx.x];
    if (i < NN) off[g * (NN + 1) + i] = inc - v;
    if (threadIdx.x == 1023) sums[g * NCH + c] = inc;
}

__global__ void k_scanB(int* __restrict__ sums) {
    int g = blockIdx.x, t = threadIdx.x;
    __shared__ int sd[128];
    int v = (t < NCH) ? sums[g * NCH + t] : 0;
    sd[t] = v;
    __syncthreads();
    for (int o = 1; o < 128; o <<= 1) {
        int a = (t >= o) ? sd[t - o] : 0;
        __syncthreads();
        sd[t] += a;
        __syncthreads();
    }
    if (t < NCH) sums[g * NCH + t] = sd[t] - v;
}

// scanC + fused rsqrt-degree computation (g==0 blocks do rn)
__global__ void k_scanC(int* __restrict__ off, const int* __restrict__ sums,
                        int* __restrict__ cur, const int* __restrict__ deg,
                        float* __restrict__ rnG, float* __restrict__ rnB) {
    int g = blockIdx.x / NCH, c = blockIdx.x % NCH;
    int i = c * 1024 + threadIdx.x;
    if (i < NN) {
        int o = off[g * (NN + 1) + i] + sums[g * NCH + c];
        off[g * (NN + 1) + i] = o;
        cur[g * NN + i] = o;
        if (g == 0) {
            int d0 = deg[i], d1 = deg[NN + i], d2 = deg[2 * NN + i];
            rnB[i]          = rsqrtf((float)max(d0, 1));
            rnB[NN + i]     = rsqrtf((float)max(d1, 1));
            rnB[2 * NN + i] = rsqrtf((float)max(d2, 1));
            rnG[i] = rsqrtf((float)max(d0 + d1 + d2, 1));
        }
    }
    if (i == NN - 1) off[g * (NN + 1) + NN] = E2;
}

// ---- adjacency placement ----
__global__ void k_place(const int* __restrict__ eu, const int* __restrict__ ei,
                        int* __restrict__ cur, int* __restrict__ adj) {
    int t = blockIdx.x * blockDim.x + threadIdx.x;
    if (t >= 3 * EE) return;
    int b = t / EE;
    int u = eu[t], it = NU + ei[t];
    int p = atomicAdd(&cur[b * NN + u], 1);
    adj[b * E2 + p] = it;
    int q = atomicAdd(&cur[b * NN + it], 1);
    adj[b * E2 + q] = u;
}

__device__ __forceinline__ void accum8(int4 raw, float* __restrict__ acc) {
    __half2* h = (__half2*)&raw;
    #pragma unroll
    for (int k = 0; k < 4; k++) {
        float2 v = __half22float2(h[k]);
        acc[2 * k]     += v.x;
        acc[2 * k + 1] += v.y;
    }
}

__device__ __forceinline__ void accum8w(int4 raw, float w, float* __restrict__ acc) {
    __half2* h = (__half2*)&raw;
    #pragma unroll
    for (int k = 0; k < 4; k++) {
        float2 v = __half22float2(h[k]);
        acc[2 * k]     += w * v.x;
        acc[2 * k + 1] += w * v.y;
    }
}

// ---- warp-per-node gather, stride-8, 2 neighbors per group in flight.
//      adj is streamed once: evict-first (__ldcs) to protect row arrays in L2.
__device__ __forceinline__ void gath4(const __half* __restrict__ inp,
                                      const int* __restrict__ adj,
                                      int s, int e, int g, int c,
                                      float* __restrict__ acc) {
    int j = s + g;
    for (; j + 4 < e; j += 8) {
        int ia = __ldcs(adj + j);
        int ib = __ldcs(adj + j + 4);
        int4 ra = __ldg((const int4*)(inp + (size_t)ia * DD + c * 8));
        int4 rb = __ldg((const int4*)(inp + (size_t)ib * DD + c * 8));
        accum8(ra, acc);
        accum8(rb, acc);
    }
    if (j < e) {
        int ia = __ldcs(adj + j);
        int4 ra = __ldg((const int4*)(inp + (size_t)ia * DD + c * 8));
        accum8(ra, acc);
    }
}

// weighted variant (w = rn[src])
__device__ __forceinline__ void gath4w(const __half* __restrict__ inp,
                                       const int* __restrict__ adj,
                                       int s, int e, const float* __restrict__ rn,
                                       int g, int c, float* __restrict__ acc) {
    int j = s + g;
    for (; j + 4 < e; j += 8) {
        int ia = __ldcs(adj + j);
        int ib = __ldcs(adj + j + 4);
        float wa = __ldg(rn + ia);
        float wb = __ldg(rn + ib);
        int4 ra = __ldg((const int4*)(inp + (size_t)ia * DD + c * 8));
        int4 rb = __ldg((const int4*)(inp + (size_t)ib * DD + c * 8));
        accum8w(ra, wa, acc);
        accum8w(rb, wb, acc);
    }
    if (j < e) {
        int ia = __ldcs(adj + j);
        float wa = __ldg(rn + ia);
        int4 ra = __ldg((const int4*)(inp + (size_t)ia * DD + c * 8));
        accum8w(ra, wa, acc);
    }
}

// butterfly-reduce acc[8] across the 4 lane groups
__device__ __forceinline__ void red4(float* __restrict__ acc) {
    #pragma unroll
    for (int k = 0; k < 8; k++) {
        acc[k] += __shfl_xor_sync(0xffffffffu, acc[k], 8);
        acc[k] += __shfl_xor_sync(0xffffffffu, acc[k], 16);
    }
}

// lanes g==0 store 8 dims (scaled) as fp16 int4
__device__ __forceinline__ void store_h(__half* __restrict__ out, size_t n,
                                        int g, int c, const float* __restrict__ acc,
                                        float scale) {
    if (g == 0) {
        __half2 h[4];
        #pragma unroll
        for (int k = 0; k < 4; k++)
            h[k] = __float22half2_rn(make_float2(acc[2 * k] * scale,
                                                 acc[2 * k + 1] * scale));
        *(int4*)(out + n * DD + c * 8) = *(int4*)h;
    }
}

// ---- global GCN layer 1: Z1 = rnG^2 * (Σ Z0[src]) ----
__global__ void k_gL1(const __half* __restrict__ z0, __half* __restrict__ z1,
                      const int* __restrict__ off, const int* __restrict__ adj,
                      const float* __restrict__ rnG) {
    int t = blockIdx.x * blockDim.x + threadIdx.x;
    int n = t >> 5;
    if (n >= NN) return;
    int lane = t & 31, g = lane >> 3, c = lane & 7;
    float acc[8] = {0, 0, 0, 0, 0, 0, 0, 0};
    #pragma unroll
    for (int gg = 0; gg < 3; gg++) {
        int s = off[gg * (NN + 1) + n], e = off[gg * (NN + 1) + n + 1];
        gath4(z0, adj + (size_t)gg * E2, s, e, g, c, acc);
    }
    red4(acc);
    float r = rnG[n];
    store_h(z1, n, g, c, acc, r * r);
}

// ---- global GCN L2 + combine: ALL = (z0/rn + z1/rn + rn*Σz1)/3 ----
__global__ void k_gL2c(const __half* __restrict__ z0, const __half* __restrict__ z1,
                       __half* __restrict__ allo, const int* __restrict__ off,
                       const int* __restrict__ adj, const float* __restrict__ rnG) {
    int t = blockIdx.x * blockDim.x + threadIdx.x;
    int n = t >> 5;
    if (n >= NN) return;
    int lane = t & 31, g = lane >> 3, c = lane & 7;
    float acc[8] = {0, 0, 0, 0, 0, 0, 0, 0};
    #pragma unroll
    for (int gg = 0; gg < 3; gg++) {
        int s = off[gg * (NN + 1) + n], e = off[gg * (NN + 1) + n + 1];
        gath4(z1, adj + (size_t)gg * E2, s, e, g, c, acc);
    }
    red4(acc);
    if (g == 0) {
        float r = rnG[n];
        float inv = 1.0f / r;
        int4 ra = __ldg((const int4*)(z0 + (size_t)n * DD + c * 8));
        int4 rb = __ldg((const int4*)(z1 + (size_t)n * DD + c * 8));
        __half2* ha = (__half2*)&ra;
        __half2* hb = (__half2*)&rb;
        const float s3 = 1.0f / 3.0f;
        __half2 hout[4];
        #pragma unroll
        for (int k = 0; k < 4; k++) {
            float2 a = __half22float2(ha[k]);
            float2 b = __half22float2(hb[k]);
            hout[k] = __float22half2_rn(
                make_float2(((a.x + b.x) * inv + acc[2 * k] * r) * s3,
                            ((a.y + b.y) * inv + acc[2 * k + 1] * r) * s3));
        }
        *(int4*)(allo + (size_t)n * DD + c * 8) = *(int4*)hout;
    }
}

// ---- branch layer 1: ZB_g = rnB_g(n)^2 * Σ rnB_g[src] * ALL[src] ----
__global__ void k_bL1(const __half* __restrict__ allo, __half* __restrict__ zb,
                      const int* __restrict__ off, const int* __restrict__ adj,
                      const float* __restrict__ rnB) {
    int t = blockIdx.x * blockDim.x + threadIdx.x;
    int q = t >> 5;
    if (q >= 3 * NN) return;
    int gg = q / NN, n = q - gg * NN;
    int lane = t & 31, g = lane >> 3, c = lane & 7;
    const float* rn = rnB + (size_t)gg * NN;
    float acc[8] = {0, 0, 0, 0, 0, 0, 0, 0};
    int s = off[gg * (NN + 1) + n], e = off[gg * (NN + 1) + n + 1];
    gath4w(allo, adj + (size_t)gg * E2, s, e, rn, g, c, acc);
    red4(acc);
    float r = rn[n];
    store_h(zb + (size_t)gg * NN * DD, n, g, c, acc, r * r);
}

// ---- branch L2 + combine + attention (users) / weighting (items) ----
__global__ void k_bL2f(const __half* __restrict__ allo, const __half* __restrict__ zb,
                       const int* __restrict__ off, const int* __restrict__ adj,
                       const float* __restrict__ rnB, const int* __restrict__ deg,
                       const float* __restrict__ W, float* __restrict__ au,
                       float* __restrict__ ifl) {
    int t = blockIdx.x * blockDim.x + threadIdx.x;
    int n = t >> 5;
    if (n >= NN) return;
    int lane = t & 31, g = lane >> 3, c = lane & 7;
    int4 ra = __ldg((const int4*)(allo + (size_t)n * DD + c * 8));
    __half2* ha = (__half2*)&ra;
    float f[3][8];
    const float s3 = 1.0f / 3.0f;
    #pragma unroll
    for (int gg = 0; gg < 3; gg++) {
        const __half* src = zb + (size_t)gg * NN * DD;
        float acc[8] = {0, 0, 0, 0, 0, 0, 0, 0};
        int s = off[gg * (NN + 1) + n], e = off[gg * (NN + 1) + n + 1];
        gath4(src, adj + (size_t)gg * E2, s, e, g, c, acc);
        red4(acc);
        float r = rnB[gg * NN + n];
        float inv = 1.0f / r;
        int4 rb = __ldg((const int4*)(src + (size_t)n * DD + c * 8));
        __half2* hb = (__half2*)&rb;
        #pragma unroll
        for (int k = 0; k < 4; k++) {
            float2 a = __half22float2(ha[k]);
            float2 b = __half22float2(hb[k]);   // zb row = rn * s1
            f[gg][2 * k]     = (a.x + b.x * inv + acc[2 * k] * r) * s3;
            f[gg][2 * k + 1] = (a.y + b.y * inv + acc[2 * k + 1] * r) * s3;
        }
    }
    if (n < NU) {
        float s00 = 0, s01 = 0, s02 = 0, s11 = 0, s12 = 0, s22 = 0;
        #pragma unroll
        for (int k = 0; k < 8; k++) {
            s00 += f[0][k] * f[0][k];
            s01 += f[0][k] * f[1][k];
            s02 += f[0][k] * f[2][k];
            s11 += f[1][k] * f[1][k];
            s12 += f[1][k] * f[2][k];
            s22 += f[2][k] * f[2][k];
        }
        #pragma unroll
        for (int o = 1; o < 8; o <<= 1) {
            s00 += __shfl_xor_sync(0xffffffffu, s00, o);
            s01 += __shfl_xor_sync(0xffffffffu, s01, o);
            s02 += __shfl_xor_sync(0xffffffffu, s02, o);
            s11 += __shfl_xor_sync(0xffffffffu, s11, o);
            s12 += __shfl_xor_sync(0xffffffffu, s12, o);
            s22 += __shfl_xor_sync(0xffffffffu, s22, o);
        }
        float l0 = s02, l1 = s12, l2 = s22;
        float q0 = l0 * l0 / (l0 * l0 + 1e-12f);
        float q1 = l1 * l1 / (l1 * l1 + 1e-12f);
        float q2 = l2 * l2 / (l2 * l2 + 1e-12f);
        float c00 = s00 * q0, c01 = s01 * q1, c02 = s02 * q2;
        float c10 = s01 * q0, c11 = s11 * q1, c12 = s12 * q2;
        float r20 = c00 + c10 + l0;
        float r21 = c01 + c11 + l1;
        float r22 = c02 + c12 + l2;
        float att[3][3] = {{c00, c01, c02}, {c10, c11, c12}, {r20, r21, r22}};
        #pragma unroll
        for (int i = 0; i < 3; i++) {
            float m = fmaxf(att[i][0], fmaxf(att[i][1], att[i][2]));
            float e0 = expf((att[i][0] - m) * 0.125f);
            float e1 = expf((att[i][1] - m) * 0.125f);
            float e2 = expf((att[i][2] - m) * 0.125f);
            float inv = 1.0f / (e0 + e1 + e2);
            att[i][0] = e0 * inv; att[i][1] = e1 * inv; att[i][2] = e2 * inv;
        }
        if (g == 0) {
            float* base = au + (size_t)n * 192;   // [u][3][64]
            #pragma unroll
            for (int i = 0; i < 3; i++) {
                float4 o0, o1;
                o0.x = att[i][0] * f[0][0] + att[i][1] * f[1][0] + att[i][2] * f[2][0];
                o0.y = att[i][0] * f[0][1] + att[i][1] * f[1][1] + att[i][2] * f[2][1];
                o0.z = att[i][0] * f[0][2] + att[i][1] * f[1][2] + att[i][2] * f[2][2];
                o0.w = att[i][0] * f[0][3] + att[i][1] * f[1][3] + att[i][2] * f[2][3];
                o1.x = att[i][0] * f[0][4] + att[i][1] * f[1][4] + att[i][2] * f[2][4];
                o1.y = att[i][0] * f[0][5] + att[i][1] * f[1][5] + att[i][2] * f[2][5];
                o1.z = att[i][0] * f[0][6] + att[i][1] * f[1][6] + att[i][2] * f[2][6];
                o1.w = att[i][0] * f[0][7] + att[i][1] * f[1][7] + att[i][2] * f[2][7];
                *(float4*)(base + i * 64 + c * 8)     = o0;
                *(float4*)(base + i * 64 + c * 8 + 4) = o1;
            }
        }
    } else {
        if (g == 0) {
            int i = n - NU;
            float w0 = (float)__ldg(deg + n)          * __ldg(W + 0);
            float w1 = (float)__ldg(deg + NN + n)     * __ldg(W + 1);
            float w2 = (float)__ldg(deg + 2 * NN + n) * __ldg(W + 2);
            float inv = 1.0f / (w0 + w1 + w2 + 1e-8f);
            w0 *= inv; w1 *= inv; w2 *= inv;
            float4 o0, o1;
            o0.x = f[0][0] * w0 + f[1][0] * w1 + f[2][0] * w2;
            o0.y = f[0][1] * w0 + f[1][1] * w1 + f[2][1] * w2;
            o0.z = f[0][2] * w0 + f[1][2] * w1 + f[2][2] * w2;
            o0.w = f[0][3] * w0 + f[1][3] * w1 + f[2][3] * w2;
            o1.x = f[0][4] * w0 + f[1][4] * w1 + f[2][4] * w2;
            o1.y = f[0][5] * w0 + f[1][5] * w1 + f[2][5] * w2;
            o1.z = f[0][6] * w0 + f[1][6] * w1 + f[2][6] * w2;
            o1.w = f[0][7] * w0 + f[1][7] * w1 + f[2][7] * w2;
            *(float4*)(ifl + (size_t)i * DD + c * 8)     = o0;
            *(float4*)(ifl + (size_t)i * DD + c * 8 + 4) = o1;
        }
    }
}

// ---- BPR loss ----
__global__ void k_bpr(const int* __restrict__ batch, const float* __restrict__ au,
                      const float* __restrict__ ifl, float* __restrict__ acc) {
    int t = blockIdx.x * blockDim.x + threadIdx.x;
    int idx = t >> 5;
    if (idx >= NB * 3) return;
    int lane = t & 31;
    int n = idx / 3, b = idx % 3;
    const int* bd = batch + n * 9 + b * 3;
    int u = bd[0], pos = bd[1], neg = bd[2];
    float2 uf = *(const float2*)(au + (size_t)u * 192 + b * 64 + 2 * lane);
    float2 p  = *(const float2*)(ifl + (size_t)pos * DD + 2 * lane);
    float2 q  = *(const float2*)(ifl + (size_t)neg * DD + 2 * lane);
    float s = uf.x * (p.x - q.x) + uf.y * (p.y - q.y);
    #pragma unroll
    for (int o = 16; o; o >>= 1) s += __shfl_xor_sync(0xffffffffu, s, o);
    if (lane == 0) {
        float sig = 1.0f / (1.0f + expf(-s));
        atomicAdd(acc, -logf(1e-10f + sig) * (1.0f / (float)NB));
    }
}

// ---- fused sum-of-squares over both embedding tables ----
__global__ void k_sumsq2(const float* __restrict__ ue, const float* __restrict__ ie,
                         float* __restrict__ acc) {
    const int NUE = NU * DD, NIE = NI * DD;
    float su = 0.0f, si = 0.0f;
    for (int i = blockIdx.x * blockDim.x + threadIdx.x; i < NUE + NIE;
         i += gridDim.x * blockDim.x) {
        if (i < NUE) { float v = ue[i]; su += v * v; }
        else         { float v = ie[i - NUE]; si += v * v; }
    }
    #pragma unroll
    for (int o = 16; o; o >>= 1) {
        su += __shfl_xor_sync(0xffffffffu, su, o);
        si += __shfl_xor_sync(0xffffffffu, si, o);
    }
    if ((threadIdx.x & 31) == 0) {
        if (su != 0.0f) atomicAdd(acc + 1, su);
        if (si != 0.0f) atomicAdd(acc + 2, si);
    }
}

__global__ void k_final(const float* __restrict__ acc, float* __restrict__ out) {
    out[0] = acc[0] + 0.001f * (sqrtf(acc[1]) + sqrtf(acc[2])) / 40001.0f;
}

extern "C" void kernel_launch(void* const* d_in, const int* in_sizes, int n_in,
                              void* d_out, int out_size) {
    const float* user_emb = (const float*)d_in[0];
    const float* item_emb = (const float*)d_in[1];
    const float* W        = (const float*)d_in[2];
    const int*   eu       = (const int*)d_in[3];
    const int*   ei       = (const int*)d_in[4];
    const int*   batch    = (const int*)d_in[5];
    float* out = (float*)d_out;

    __half *Z0, *Z1, *ALLh, *ZB;
    float *AU, *IF, *rnG, *rnB, *ACC;
    int *adj, *deg, *off, *cur, *sums;
    cudaGetSymbolAddress((void**)&Z0,   d_Z0);
    cudaGetSymbolAddress((void**)&Z1,   d_Z1);
    cudaGetSymbolAddress((void**)&ALLh, d_ALLh);
    cudaGetSymbolAddress((void**)&ZB,   d_ZB);
    cudaGetSymbolAddress((void**)&AU,   d_AU);
    cudaGetSymbolAddress((void**)&IF,   d_IF);
    cudaGetSymbolAddress((void**)&rnG,  d_rnG);
    cudaGetSymbolAddress((void**)&rnB,  d_rnB);
    cudaGetSymbolAddress((void**)&ACC,  d_ACC);
    cudaGetSymbolAddress((void**)&adj,  d_adj);
    cudaGetSymbolAddress((void**)&deg,  d_deg);
    cudaGetSymbolAddress((void**)&off,  d_off);
    cudaGetSymbolAddress((void**)&cur,  d_cur);
    cudaGetSymbolAddress((void**)&sums, d_sums);

    const int NTH = 256;
    auto blocksFor = [](long threads) { return (int)((threads + 255) / 256); };

    // ---- CSR build (+degree norms fused into scanC) ----
    cudaMemsetAsync(deg, 0, 3 * NN * sizeof(int));
    k_degcnt<<<blocksFor(3L * EE), NTH>>>(eu, ei, deg);
    k_scanA<<<3 * NCH, 1024>>>(deg, off, sums);
    k_scanB<<<3, 128>>>(sums);
    k_scanC<<<3 * NCH, 1024>>>(off, sums, cur, deg, rnG, rnB);
    k_place<<<blocksFor(3L * EE), NTH>>>(eu, ei, cur, adj);

    // Z0 = rnG * concat(user_emb, item_emb)
    k_conv<<<blocksFor((long)NN * DD / 2), NTH>>>(user_emb, item_emb, rnG, Z0);

    // ---- global LightGCN ----
    k_gL1<<<blocksFor((long)NN * 32), NTH>>>(Z0, Z1, off, adj, rnG);
    k_gL2c<<<blocksFor((long)NN * 32), NTH>>>(Z0, Z1, ALLh, off, adj, rnG);

    // ---- branch LightGCNs ----
    k_bL1<<<blocksFor(3L * NN * 32), NTH>>>(ALLh, ZB, off, adj, rnB);
    k_bL2f<<<blocksFor((long)NN * 32), NTH>>>(ALLh, ZB, off, adj, rnB, deg, W, AU, IF);

    // ---- losses ----
    cudaMemsetAsync(ACC, 0, 4 * sizeof(float));
    k_bpr<<<blocksFor((long)NB * 3 * 32), NTH>>>(batch, AU, IF, ACC);
    k_sumsq2<<<512, NTH>>>(user_emb, item_emb, ACC);
    k_final<<<1, 1>>>(ACC, out);
}

// round 13
// speedup vs baseline: 1.2240x; 1.0508x over previous
#include <cuda_runtime.h>
#include <cuda_fp16.h>
#include <math.h>

#define NU 60001
#define NI 40001
#define NN 100002
#define DD 64
#define EE 600000
#define E2 (2*EE)
#define NB 2048
#define NCH 98   // ceil(NN/1024)

// ---- static device scratch ----
__device__ __align__(128) __half d_Z0 [NN * DD];      // rnG-scaled x0
__device__ __align__(128) __half d_Z1 [NN * DD];      // rnG^2 * s1
__device__ __align__(128) __half d_ALLh[NN * DD];     // plain ALL (shared hot gather src)
__device__ __align__(128) __half d_ZB [3 * NN * DD];  // rnB_g * s1_g (pre-scaled)
__device__ __align__(128) float  d_AU [NU * 3 * DD];  // all_user [u][3][64]
__device__ __align__(128) float  d_IF [NI * DD];      // item_final [i][64]
__device__ __align__(128) int    d_adj [3 * E2];
__device__ __align__(128) int    d_deg [3 * NN];
__device__ __align__(128) int    d_off [3 * (NN + 1)];
__device__ __align__(128) int    d_cur [3 * NN];
__device__ __align__(128) int    d_sums[3 * NCH];
__device__ __align__(128) float  d_rnG [NN];
__device__ __align__(128) float  d_rnB [3 * NN];
__device__ float d_ACC[4];

// ---- convert inputs to fp16, pre-scaled by rnG ----
__global__ void k_conv(const float* __restrict__ ue, const float* __restrict__ ie,
                       const float* __restrict__ rnG, __half* __restrict__ z0) {
    int i = blockIdx.x * blockDim.x + threadIdx.x;       // half2 index
    if (i >= NN * DD / 2) return;
    int elem = i * 2;
    int n = i >> 5;
    const int UB = NU * DD;
    float2 v = (elem < UB) ? __ldg((const float2*)(ue + elem))
                           : __ldg((const float2*)(ie + (elem - UB)));
    float r = __ldg(rnG + n);
    ((__half2*)z0)[i] = __float22half2_rn(make_float2(v.x * r, v.y * r));
}

// ---- degree count ----
__global__ void k_degcnt(const int* __restrict__ eu, const int* __restrict__ ei,
                         int* __restrict__ deg) {
    int t = blockIdx.x * blockDim.x + threadIdx.x;
    if (t >= 3 * EE) return;
    int b = t / EE;
    atomicAdd(&deg[b * NN + eu[t]], 1);
    atomicAdd(&deg[b * NN + NU + ei[t]], 1);
}

// ---- 3-pass exclusive scan ----
__global__ void k_scanA(const int* __restrict__ deg, int* __restrict__ off,
                        int* __restrict__ sums) {
    int g = blockIdx.x / NCH, c = blockIdx.x % NCH;
    int i = c * 1024 + threadIdx.x;
    int v = (i < NN) ? deg[g * NN + i] : 0;
    __shared__ int sd[1024];
    sd[threadIdx.x] = v;
    __syncthreads();
    for (int o = 1; o < 1024; o <<= 1) {
        int a = (threadIdx.x >= o) ? sd[threadIdx.x - o] : 0;
        __syncthreads();
        sd[threadIdx.x] += a;
        __syncthreads();
    }
    int inc = sd[threadIdx.x];
    if (i < NN) off[g * (NN + 1) + i] = inc - v;
    if (threadIdx.x == 1023) sums[g * NCH + c] = inc;
}

__global__ void k_scanB(int* __restrict__ sums) {
    int g = blockIdx.x, t = threadIdx.x;
    __shared__ int sd[128];
    int v = (t < NCH) ? sums[g * NCH + t] : 0;
    sd[t] = v;
    __syncthreads();
    for (int o = 1; o < 128; o <<= 1) {
        int a = (t >= o) ? sd[t - o] : 0;
        __syncthreads();
        sd[t] += a;
        __syncthreads();
    }
    if (t < NCH) sums[g * NCH + t] = sd[t] - v;
}

// scanC + fused rsqrt-degree computation (g==0 blocks do rn)
__global__ void k_scanC(int* __restrict__ off, const int* __restrict__ sums,
                        int* __restrict__ cur, const int* __restrict__ deg,
                        float* __restrict__ rnG, float* __restrict__ rnB) {
    int g = blockIdx.x / NCH, c = blockIdx.x % NCH;
    int i = c * 1024 + threadIdx.x;
    if (i < NN) {
        int o = off[g * (NN + 1) + i] + sums[g * NCH + c];
        off[g * (NN + 1) + i] = o;
        cur[g * NN + i] = o;
        if (g == 0) {
            int d0 = deg[i], d1 = deg[NN + i], d2 = deg[2 * NN + i];
            rnB[i]          = rsqrtf((float)max(d0, 1));
            rnB[NN + i]     = rsqrtf((float)max(d1, 1));
            rnB[2 * NN + i] = rsqrtf((float)max(d2, 1));
            rnG[i] = rsqrtf((float)max(d0 + d1 + d2, 1));
        }
    }
    if (i == NN - 1) off[g * (NN + 1) + NN] = E2;
}

// ---- adjacency placement ----
__global__ void k_place(const int* __restrict__ eu, const int* __restrict__ ei,
                        int* __restrict__ cur, int* __restrict__ adj) {
    int t = blockIdx.x * blockDim.x + threadIdx.x;
    if (t >= 3 * EE) return;
    int b = t / EE;
    int u = eu[t], it = NU + ei[t];
    int p = atomicAdd(&cur[b * NN + u], 1);
    adj[b * E2 + p] = it;
    int q = atomicAdd(&cur[b * NN + it], 1);
    adj[b * E2 + q] = u;
}

__device__ __forceinline__ void accum8w(int4 raw, float w, float* __restrict__ acc) {
    __half2* h = (__half2*)&raw;
    #pragma unroll
    for (int k = 0; k < 4; k++) {
        float2 v = __half22float2(h[k]);
        acc[2 * k]     += w * v.x;
        acc[2 * k + 1] += w * v.y;
    }
}

// ---- warp-per-node gather, depth-4 with CLAMPED in-range indices.
//      All loads unconditional; inactive slots re-load adj[e-1] (valid, aligned)
//      with weight 0 — exact numeric no-op, keeps 4 rows in flight per group.
__device__ __forceinline__ void gath4(const __half* __restrict__ inp,
                                      const int* __restrict__ adj,
                                      int s, int e, int g, int c,
                                      float* __restrict__ acc) {
    int last = e - 1;
    for (int j = s + g; j < e; j += 16) {
        int j1 = j + 4, j2 = j + 8, j3 = j + 12;
        float w1 = (j1 <= last) ? 1.0f : 0.0f;
        float w2 = (j2 <= last) ? 1.0f : 0.0f;
        float w3 = (j3 <= last) ? 1.0f : 0.0f;
        j1 = min(j1, last); j2 = min(j2, last); j3 = min(j3, last);
        int i0 = __ldg(adj + j);
        int i1 = __ldg(adj + j1);
        int i2 = __ldg(adj + j2);
        int i3 = __ldg(adj + j3);
        int4 r0 = __ldg((const int4*)(inp + (size_t)i0 * DD + c * 8));
        int4 r1 = __ldg((const int4*)(inp + (size_t)i1 * DD + c * 8));
        int4 r2 = __ldg((const int4*)(inp + (size_t)i2 * DD + c * 8));
        int4 r3 = __ldg((const int4*)(inp + (size_t)i3 * DD + c * 8));
        accum8w(r0, 1.0f, acc);
        accum8w(r1, w1, acc);
        accum8w(r2, w2, acc);
        accum8w(r3, w3, acc);
    }
}

// weighted variant (w = rn[src]); inactive slots get weight 0
__device__ __forceinline__ void gath4w(const __half* __restrict__ inp,
                                       const int* __restrict__ adj,
                                       int s, int e, const float* __restrict__ rn,
                                       int g, int c, float* __restrict__ acc) {
    int last = e - 1;
    for (int j = s + g; j < e; j += 16) {
        int j1 = j + 4, j2 = j + 8, j3 = j + 12;
        float m1 = (j1 <= last) ? 1.0f : 0.0f;
        float m2 = (j2 <= last) ? 1.0f : 0.0f;
        float m3 = (j3 <= last) ? 1.0f : 0.0f;
        j1 = min(j1, last); j2 = min(j2, last); j3 = min(j3, last);
        int i0 = __ldg(adj + j);
        int i1 = __ldg(adj + j1);
        int i2 = __ldg(adj + j2);
        int i3 = __ldg(adj + j3);
        float w0 = __ldg(rn + i0);
        float w1 = __ldg(rn + i1) * m1;
        float w2 = __ldg(rn + i2) * m2;
        float w3 = __ldg(rn + i3) * m3;
        int4 r0 = __ldg((const int4*)(inp + (size_t)i0 * DD + c * 8));
        int4 r1 = __ldg((const int4*)(inp + (size_t)i1 * DD + c * 8));
        int4 r2 = __ldg((const int4*)(inp + (size_t)i2 * DD + c * 8));
        int4 r3 = __ldg((const int4*)(inp + (size_t)i3 * DD + c * 8));
        accum8w(r0, w0, acc);
        accum8w(r1, w1, acc);
        accum8w(r2, w2, acc);
        accum8w(r3, w3, acc);
    }
}

// butterfly-reduce acc[8] across the 4 lane groups
__device__ __forceinline__ void red4(float* __restrict__ acc) {
    #pragma unroll
    for (int k = 0; k < 8; k++) {
        acc[k] += __shfl_xor_sync(0xffffffffu, acc[k], 8);
        acc[k] += __shfl_xor_sync(0xffffffffu, acc[k], 16);
    }
}

// lanes g==0 store 8 dims (scaled) as fp16 int4
__device__ __forceinline__ void store_h(__half* __restrict__ out, size_t n,
                                        int g, int c, const float* __restrict__ acc,
                                        float scale) {
    if (g == 0) {
        __half2 h[4];
        #pragma unroll
        for (int k = 0; k < 4; k++)
            h[k] = __float22half2_rn(make_float2(acc[2 * k] * scale,
                                                 acc[2 * k + 1] * scale));
        *(int4*)(out + n * DD + c * 8) = *(int4*)h;
    }
}

// ---- global GCN layer 1: Z1 = rnG^2 * (Σ Z0[src]) ----
__global__ void k_gL1(const __half* __restrict__ z0, __half* __restrict__ z1,
                      const int* __restrict__ off, const int* __restrict__ adj,
                      const float* __restrict__ rnG) {
    int t = blockIdx.x * blockDim.x + threadIdx.x;
    int n = t >> 5;
    if (n >= NN) return;
    int lane = t & 31, g = lane >> 3, c = lane & 7;
    float acc[8] = {0, 0, 0, 0, 0, 0, 0, 0};
    #pragma unroll
    for (int gg = 0; gg < 3; gg++) {
        int s = off[gg * (NN + 1) + n], e = off[gg * (NN + 1) + n + 1];
        gath4(z0, adj + (size_t)gg * E2, s, e, g, c, acc);
    }
    red4(acc);
    float r = rnG[n];
    store_h(z1, n, g, c, acc, r * r);
}

// ---- global GCN L2 + combine: ALL = (z0/rn + z1/rn + rn*Σz1)/3 ----
__global__ void k_gL2c(const __half* __restrict__ z0, const __half* __restrict__ z1,
                       __half* __restrict__ allo, const int* __restrict__ off,
                       const int* __restrict__ adj, const float* __restrict__ rnG) {
    int t = blockIdx.x * blockDim.x + threadIdx.x;
    int n = t >> 5;
    if (n >= NN) return;
    int lane = t & 31, g = lane >> 3, c = lane & 7;
    float acc[8] = {0, 0, 0, 0, 0, 0, 0, 0};
    #pragma unroll
    for (int gg = 0; gg < 3; gg++) {
        int s = off[gg * (NN + 1) + n], e = off[gg * (NN + 1) + n + 1];
        gath4(z1, adj + (size_t)gg * E2, s, e, g, c, acc);
    }
    red4(acc);
    if (g == 0) {
        float r = rnG[n];
        float inv = 1.0f / r;
        int4 ra = __ldg((const int4*)(z0 + (size_t)n * DD + c * 8));
        int4 rb = __ldg((const int4*)(z1 + (size_t)n * DD + c * 8));
        __half2* ha = (__half2*)&ra;
        __half2* hb = (__half2*)&rb;
        const float s3 = 1.0f / 3.0f;
        __half2 hout[4];
        #pragma unroll
        for (int k = 0; k < 4; k++) {
            float2 a = __half22float2(ha[k]);
            float2 b = __half22float2(hb[k]);
            hout[k] = __float22half2_rn(
                make_float2(((a.x + b.x) * inv + acc[2 * k] * r) * s3,
                            ((a.y + b.y) * inv + acc[2 * k + 1] * r) * s3));
        }
        *(int4*)(allo + (size_t)n * DD + c * 8) = *(int4*)hout;
    }
}

// ---- branch layer 1: ZB_g = rnB_g(n)^2 * Σ rnB_g[src] * ALL[src] ----
__global__ void k_bL1(const __half* __restrict__ allo, __half* __restrict__ zb,
                      const int* __restrict__ off, const int* __restrict__ adj,
                      const float* __restrict__ rnB) {
    int t = blockIdx.x * blockDim.x + threadIdx.x;
    int q = t >> 5;
    if (q >= 3 * NN) return;
    int gg = q / NN, n = q - gg * NN;
    int lane = t & 31, g = lane >> 3, c = lane & 7;
    const float* rn = rnB + (size_t)gg * NN;
    float acc[8] = {0, 0, 0, 0, 0, 0, 0, 0};
    int s = off[gg * (NN + 1) + n], e = off[gg * (NN + 1) + n + 1];
    gath4w(allo, adj + (size_t)gg * E2, s, e, rn, g, c, acc);
    red4(acc);
    float r = rn[n];
    store_h(zb + (size_t)gg * NN * DD, n, g, c, acc, r * r);
}

// ---- branch L2 + combine + attention (users) / weighting (items) ----
__global__ void k_bL2f(const __half* __restrict__ allo, const __half* __restrict__ zb,
                       const int* __restrict__ off, const int* __restrict__ adj,
                       const float* __restrict__ rnB, const int* __restrict__ deg,
                       const float* __restrict__ W, float* __restrict__ au,
                       float* __restrict__ ifl) {
    int t = blockIdx.x * blockDim.x + threadIdx.x;
    int n = t >> 5;
    if (n >= NN) return;
    int lane = t & 31, g = lane >> 3, c = lane & 7;
    int4 ra = __ldg((const int4*)(allo + (size_t)n * DD + c * 8));
    __half2* ha = (__half2*)&ra;
    float f[3][8];
    const float s3 = 1.0f / 3.0f;
    #pragma unroll
    for (int gg = 0; gg < 3; gg++) {
        const __half* src = zb + (size_t)gg * NN * DD;
        float acc[8] = {0, 0, 0, 0, 0, 0, 0, 0};
        int s = off[gg * (NN + 1) + n], e = off[gg * (NN + 1) + n + 1];
        gath4(src, adj + (size_t)gg * E2, s, e, g, c, acc);
        red4(acc);
        float r = rnB[gg * NN + n];
        float inv = 1.0f / r;
        int4 rb = __ldg((const int4*)(src + (size_t)n * DD + c * 8));
        __half2* hb = (__half2*)&rb;
        #pragma unroll
        for (int k = 0; k < 4; k++) {
            float2 a = __half22float2(ha[k]);
            float2 b = __half22float2(hb[k]);   // zb row = rn * s1
            f[gg][2 * k]     = (a.x + b.x * inv + acc[2 * k] * r) * s3;
            f[gg][2 * k + 1] = (a.y + b.y * inv + acc[2 * k + 1] * r) * s3;
        }
    }
    if (n < NU) {
        float s00 = 0, s01 = 0, s02 = 0, s11 = 0, s12 = 0, s22 = 0;
        #pragma unroll
        for (int k = 0; k < 8; k++) {
            s00 += f[0][k] * f[0][k];
            s01 += f[0][k] * f[1][k];
            s02 += f[0][k] * f[2][k];
            s11 += f[1][k] * f[1][k];
            s12 += f[1][k] * f[2][k];
            s22 += f[2][k] * f[2][k];
        }
        #pragma unroll
        for (int o = 1; o < 8; o <<= 1) {
            s00 += __shfl_xor_sync(0xffffffffu, s00, o);
            s01 += __shfl_xor_sync(0xffffffffu, s01, o);
            s02 += __shfl_xor_sync(0xffffffffu, s02, o);
            s11 += __shfl_xor_sync(0xffffffffu, s11, o);
            s12 += __shfl_xor_sync(0xffffffffu, s12, o);
            s22 += __shfl_xor_sync(0xffffffffu, s22, o);
        }
        float l0 = s02, l1 = s12, l2 = s22;
        float q0 = l0 * l0 / (l0 * l0 + 1e-12f);
        float q1 = l1 * l1 / (l1 * l1 + 1e-12f);
        float q2 = l2 * l2 / (l2 * l2 + 1e-12f);
        float c00 = s00 * q0, c01 = s01 * q1, c02 = s02 * q2;
        float c10 = s01 * q0, c11 = s11 * q1, c12 = s12 * q2;
        float r20 = c00 + c10 + l0;
        float r21 = c01 + c11 + l1;
        float r22 = c02 + c12 + l2;
        float att[3][3] = {{c00, c01, c02}, {c10, c11, c12}, {r20, r21, r22}};
        #pragma unroll
        for (int i = 0; i < 3; i++) {
            float m = fmaxf(att[i][0], fmaxf(att[i][1], att[i][2]));
            float e0 = expf((att[i][0] - m) * 0.125f);
            float e1 = expf((att[i][1] - m) * 0.125f);
            float e2 = expf((att[i][2] - m) * 0.125f);
            float inv = 1.0f / (e0 + e1 + e2);
            att[i][0] = e0 * inv; att[i][1] = e1 * inv; att[i][2] = e2 * inv;
        }
        if (g == 0) {
            float* base = au + (size_t)n * 192;   // [u][3][64]
            #pragma unroll
            for (int i = 0; i < 3; i++) {
                float4 o0, o1;
                o0.x = att[i][0] * f[0][0] + att[i][1] * f[1][0] + att[i][2] * f[2][0];
                o0.y = att[i][0] * f[0][1] + att[i][1] * f[1][1] + att[i][2] * f[2][1];
                o0.z = att[i][0] * f[0][2] + att[i][1] * f[1][2] + att[i][2] * f[2][2];
                o0.w = att[i][0] * f[0][3] + att[i][1] * f[1][3] + att[i][2] * f[2][3];
                o1.x = att[i][0] * f[0][4] + att[i][1] * f[1][4] + att[i][2] * f[2][4];
                o1.y = att[i][0] * f[0][5] + att[i][1] * f[1][5] + att[i][2] * f[2][5];
                o1.z = att[i][0] * f[0][6] + att[i][1] * f[1][6] + att[i][2] * f[2][6];
                o1.w = att[i][0] * f[0][7] + att[i][1] * f[1][7] + att[i][2] * f[2][7];
                *(float4*)(base + i * 64 + c * 8)     = o0;
                *(float4*)(base + i * 64 + c * 8 + 4) = o1;
            }
        }
    } else {
        if (g == 0) {
            int i = n - NU;
            float w0 = (float)__ldg(deg + n)          * __ldg(W + 0);
            float w1 = (float)__ldg(deg + NN + n)     * __ldg(W + 1);
            float w2 = (float)__ldg(deg + 2 * NN + n) * __ldg(W + 2);
            float inv = 1.0f / (w0 + w1 + w2 + 1e-8f);
            w0 *= inv; w1 *= inv; w2 *= inv;
            float4 o0, o1;
            o0.x = f[0][0] * w0 + f[1][0] * w1 + f[2][0] * w2;
            o0.y = f[0][1] * w0 + f[1][1] * w1 + f[2][1] * w2;
            o0.z = f[0][2] * w0 + f[1][2] * w1 + f[2][2] * w2;
            o0.w = f[0][3] * w0 + f[1][3] * w1 + f[2][3] * w2;
            o1.x = f[0][4] * w0 + f[1][4] * w1 + f[2][4] * w2;
            o1.y = f[0][5] * w0 + f[1][5] * w1 + f[2][5] * w2;
            o1.z = f[0][6] * w0 + f[1][6] * w1 + f[2][6] * w2;
            o1.w = f[0][7] * w0 + f[1][7] * w1 + f[2][7] * w2;
            *(float4*)(ifl + (size_t)i * DD + c * 8)     = o0;
            *(float4*)(ifl + (size_t)i * DD + c * 8 + 4) = o1;
        }
    }
}

// ---- BPR loss ----
__global__ void k_bpr(const int* __restrict__ batch, const float* __restrict__ au,
                      const float* __restrict__ ifl, float* __restrict__ acc) {
    int t = blockIdx.x * blockDim.x + threadIdx.x;
    int idx = t >> 5;
    if (idx >= NB * 3) return;
    int lane = t & 31;
    int n = idx / 3, b = idx % 3;
    const int* bd = batch + n * 9 + b * 3;
    int u = bd[0], pos = bd[1], neg = bd[2];
    float2 uf = *(const float2*)(au + (size_t)u * 192 + b * 64 + 2 * lane);
    float2 p  = *(const float2*)(ifl + (size_t)pos * DD + 2 * lane);
    float2 q  = *(const float2*)(ifl + (size_t)neg * DD + 2 * lane);
    float s = uf.x * (p.x - q.x) + uf.y * (p.y - q.y);
    #pragma unroll
    for (int o = 16; o; o >>= 1) s += __shfl_xor_sync(0xffffffffu, s, o);
    if (lane == 0) {
        float sig = 1.0f / (1.0f + expf(-s));
        atomicAdd(acc, -logf(1e-10f + sig) * (1.0f / (float)NB));
    }
}

// ---- fused sum-of-squares over both embedding tables ----
__global__ void k_sumsq2(const float* __restrict__ ue, const float* __restrict__ ie,
                         float* __restrict__ acc) {
    const int NUE = NU * DD, NIE = NI * DD;
    float su = 0.0f, si = 0.0f;
    for (int i = blockIdx.x * blockDim.x + threadIdx.x; i < NUE + NIE;
         i += gridDim.x * blockDim.x) {
        if (i < NUE) { float v = ue[i]; su += v * v; }
        else         { float v = ie[i - NUE]; si += v * v; }
    }
    #pragma unroll
    for (int o = 16; o; o >>= 1) {
        su += __shfl_xor_sync(0xffffffffu, su, o);
        si += __shfl_xor_sync(0xffffffffu, si, o);
    }
    if ((threadIdx.x & 31) == 0) {
        if (su != 0.0f) atomicAdd(acc + 1, su);
        if (si != 0.0f) atomicAdd(acc + 2, si);
    }
}

__global__ void k_final(const float* __restrict__ acc, float* __restrict__ out) {
    out[0] = acc[0] + 0.001f * (sqrtf(acc[1]) + sqrtf(acc[2])) / 40001.0f;
}

extern "C" void kernel_launch(void* const* d_in, const int* in_sizes, int n_in,
                              void* d_out, int out_size) {
    const float* user_emb = (const float*)d_in[0];
    const float* item_emb = (const float*)d_in[1];
    const float* W        = (const float*)d_in[2];
    const int*   eu       = (const int*)d_in[3];
    const int*   ei       = (const int*)d_in[4];
    const int*   batch    = (const int*)d_in[5];
    float* out = (float*)d_out;

    __half *Z0, *Z1, *ALLh, *ZB;
    float *AU, *IF, *rnG, *rnB, *ACC;
    int *adj, *deg, *off, *cur, *sums;
    cudaGetSymbolAddress((void**)&Z0,   d_Z0);
    cudaGetSymbolAddress((void**)&Z1,   d_Z1);
    cudaGetSymbolAddress((void**)&ALLh, d_ALLh);
    cudaGetSymbolAddress((void**)&ZB,   d_ZB);
    cudaGetSymbolAddress((void**)&AU,   d_AU);
    cudaGetSymbolAddress((void**)&IF,   d_IF);
    cudaGetSymbolAddress((void**)&rnG,  d_rnG);
    cudaGetSymbolAddress((void**)&rnB,  d_rnB);
    cudaGetSymbolAddress((void**)&ACC,  d_ACC);
    cudaGetSymbolAddress((void**)&adj,  d_adj);
    cudaGetSymbolAddress((void**)&deg,  d_deg);
    cudaGetSymbolAddress((void**)&off,  d_off);
    cudaGetSymbolAddress((void**)&cur,  d_cur);
    cudaGetSymbolAddress((void**)&sums, d_sums);

    const int NTH = 256;
    auto blocksFor = [](long threads) { return (int)((threads + 255) / 256); };

    // ---- CSR build (+degree norms fused into scanC) ----
    cudaMemsetAsync(deg, 0, 3 * NN * sizeof(int));
    k_degcnt<<<blocksFor(3L * EE), NTH>>>(eu, ei, deg);
    k_scanA<<<3 * NCH, 1024>>>(deg, off, sums);
    k_scanB<<<3, 128>>>(sums);
    k_scanC<<<3 * NCH, 1024>>>(off, sums, cur, deg, rnG, rnB);
    k_place<<<blocksFor(3L * EE), NTH>>>(eu, ei, cur, adj);

    // Z0 = rnG * concat(user_emb, item_emb)
    k_conv<<<blocksFor((long)NN * DD / 2), NTH>>>(user_emb, item_emb, rnG, Z0);

    // ---- global LightGCN ----
    k_gL1<<<blocksFor((long)NN * 32), NTH>>>(Z0, Z1, off, adj, rnG);
    k_gL2c<<<blocksFor((long)NN * 32), NTH>>>(Z0, Z1, ALLh, off, adj, rnG);

    // ---- branch LightGCNs ----
    k_bL1<<<blocksFor(3L * NN * 32), NTH>>>(ALLh, ZB, off, adj, rnB);
    k_bL2f<<<blocksFor((long)NN * 32), NTH>>>(ALLh, ZB, off, adj, rnB, deg, W, AU, IF);

    // ---- losses ----
    cudaMemsetAsync(ACC, 0, 4 * sizeof(float));
    k_bpr<<<blocksFor((long)NB * 3 * 32), NTH>>>(batch, AU, IF, ACC);
    k_sumsq2<<<512, NTH>>>(user_emb, item_emb, ACC);
    k_final<<<1, 1>>>(ACC, out);
}